// round 7
// baseline (speedup 1.0000x reference)
#include <cuda_runtime.h>
#include <cuda_bf16.h>
#include <math_constants.h>
#include <cstdint>

#define NB 32
#define NT 512
#define ND 512
#define NV 1024
#define NL 128
#define NS 257      // 2*NL+1
#define SPAD 288    // padded S stride
#define NM (NB*NT)  // 16384 rows
#define GST 132     // g_gather row stride (129 used)

// Scratch (allocation-free per harness rules)
__device__ float g_pext[(size_t)NM * SPAD];          // 18.9 MB
__device__ float g_loss[NB];
__device__ __nv_bfloat16 g_xb[(size_t)NM * ND];      // 16 MB  (x in bf16)
__device__ __nv_bfloat16 g_wt[(size_t)NV * ND];      // 1 MB   (W^T bf16 [V][D])
__device__ float2 g_part[(size_t)NM * 8];            // per-row, per-slice (max, sumexp)
__device__ float g_gather[(size_t)NM * GST];         // per-row gathered exp(lg - m_slice)

// ---------------------------------------------------------------------------
// PTX helpers (portable: cp.async sm_80+, ldmatrix sm_75+, mma.bf16 sm_80+)
// ---------------------------------------------------------------------------
__device__ __forceinline__ uint32_t smem_u32(const void* p) {
    uint32_t a;
    asm("{ .reg .u64 t; cvta.to.shared.u64 t, %1; cvt.u32.u64 %0, t; }" : "=r"(a) : "l"(p));
    return a;
}
#define CP_ASYNC16(dst, src) \
    asm volatile("cp.async.cg.shared.global [%0], [%1], 16;" :: "r"(dst), "l"(src))
#define CP_COMMIT() asm volatile("cp.async.commit_group;" ::: "memory")
#define CP_WAIT2()  asm volatile("cp.async.wait_group 2;" ::: "memory")

#define LDSM_X4(r0, r1, r2, r3, addr) \
    asm volatile("ldmatrix.sync.aligned.m8n8.x4.shared.b16 {%0,%1,%2,%3}, [%4];" \
                 : "=r"(r0), "=r"(r1), "=r"(r2), "=r"(r3) : "r"(addr))

#define MMA16816(d, a0, a1, a2, a3, b0, b1) \
    asm volatile("mma.sync.aligned.m16n8k16.row.col.f32.bf16.bf16.f32 " \
                 "{%0,%1,%2,%3}, {%4,%5,%6,%7}, {%8,%9}, {%0,%1,%2,%3};" \
                 : "+f"((d)[0]), "+f"((d)[1]), "+f"((d)[2]), "+f"((d)[3]) \
                 : "r"(a0), "r"(a1), "r"(a2), "r"(a3), "r"(b0), "r"(b1))

// ---------------------------------------------------------------------------
// Convert x -> bf16
// ---------------------------------------------------------------------------
__global__ __launch_bounds__(256) void convert_x_kernel(const float* __restrict__ x) {
    size_t i = ((size_t)blockIdx.x * 256 + threadIdx.x) * 4;
    float4 v = *(const float4*)(x + i);
    __nv_bfloat162 a = __floats2bfloat162_rn(v.x, v.y);
    __nv_bfloat162 b = __floats2bfloat162_rn(v.z, v.w);
    *(__nv_bfloat162*)(g_xb + i) = a;
    *(__nv_bfloat162*)(g_xb + i + 2) = b;
}

// ---------------------------------------------------------------------------
// Convert + transpose W[D][V] fp32 -> g_wt[V][D] bf16
// ---------------------------------------------------------------------------
__global__ __launch_bounds__(256) void convert_w_kernel(const float* __restrict__ W) {
    __shared__ float t[32][33];
    int tx = threadIdx.x, ty = threadIdx.y;
    int n0 = blockIdx.x * 32, k0 = blockIdx.y * 32;
#pragma unroll
    for (int j = 0; j < 32; j += 8)
        t[ty + j][tx] = W[(size_t)(k0 + ty + j) * NV + n0 + tx];
    __syncthreads();
#pragma unroll
    for (int j = 0; j < 32; j += 8)
        g_wt[(size_t)(n0 + ty + j) * ND + k0 + tx] = __float2bfloat16(t[tx][ty + j]);
}

// ---------------------------------------------------------------------------
// Kernel 1: bf16 HMMA GEMM (CTA 128x128, 8 warps, 4-stage cp.async pipeline)
//   FUSED EPILOGUE: tile -> smem, per-slice softmax partials + label gather.
//   No logits are materialized in global memory.
// ---------------------------------------------------------------------------
#define KSTAGE 32
#define SROW 40           // padded row stride in bf16 elems (80 bytes)
#define PSTAGES 4
#define STAGE_BYTES (128 * SROW * 2)            // 10240 B per tile
#define GEMM_SMEM (PSTAGES * STAGE_BYTES * 2)   // 81920 B (also covers 128*132*4)

__global__ __launch_bounds__(256) void gemm_hmma_kernel(const float* __restrict__ bias,
                                                        const int* __restrict__ target) {
    extern __shared__ __align__(16) char smem[];

    const int tid = threadIdx.x, wid = tid >> 5, lane = tid & 31;
    const int bx = blockIdx.x;           // N slice (0..7)
    const int by = blockIdx.y;           // M tile (0..127)
    const int mBase = by * 128, nBase = bx * 128;
    const int wm = (wid >> 2) * 64;      // warp M offset in tile
    const int wn = (wid & 3) * 32;       // warp N offset in tile

    const __nv_bfloat16* Ag = g_xb + (size_t)mBase * ND;
    const __nv_bfloat16* Bg = g_wt + (size_t)nBase * ND;

    uint32_t sA0 = smem_u32(smem);
    uint32_t sB0 = sA0 + PSTAGES * STAGE_BYTES;

    const int ld_r0 = tid >> 2, ld_c0 = (tid & 3);
    const int ld_r1 = (tid + 256) >> 2, ld_c1 = ((tid + 256) & 3);

    const int NSTAGES = ND / KSTAGE;   // 16

#pragma unroll
    for (int s = 0; s < PSTAGES - 1; s++) {
        const __nv_bfloat16* Ags = Ag + s * KSTAGE;
        const __nv_bfloat16* Bgs = Bg + s * KSTAGE;
        uint32_t sAn = sA0 + s * STAGE_BYTES;
        uint32_t sBn = sB0 + s * STAGE_BYTES;
        CP_ASYNC16(sAn + ld_r0 * 80 + ld_c0 * 16, Ags + (size_t)ld_r0 * ND + ld_c0 * 8);
        CP_ASYNC16(sAn + ld_r1 * 80 + ld_c1 * 16, Ags + (size_t)ld_r1 * ND + ld_c1 * 8);
        CP_ASYNC16(sBn + ld_r0 * 80 + ld_c0 * 16, Bgs + (size_t)ld_r0 * ND + ld_c0 * 8);
        CP_ASYNC16(sBn + ld_r1 * 80 + ld_c1 * 16, Bgs + (size_t)ld_r1 * ND + ld_c1 * 8);
        CP_COMMIT();
    }

    float acc[4][4][4];
#pragma unroll
    for (int i = 0; i < 4; i++)
#pragma unroll
        for (int j = 0; j < 4; j++)
#pragma unroll
            for (int r = 0; r < 4; r++) acc[i][j][r] = 0.f;

    uint32_t aoff = (uint32_t)((wm + (lane & 15)) * 80 + (lane >> 4) * 16);
    uint32_t boff = (uint32_t)((wn + ((lane >> 4) & 1) * 8 + (lane & 7)) * 80 +
                               ((lane >> 3) & 1) * 16);

#pragma unroll 1
    for (int ks = 0; ks < NSTAGES; ks++) {
        int buf = ks & (PSTAGES - 1);
        CP_WAIT2();
        __syncthreads();

        int sf = ks + PSTAGES - 1;
        if (sf < NSTAGES) {
            int nb = sf & (PSTAGES - 1);
            const __nv_bfloat16* Ags = Ag + sf * KSTAGE;
            const __nv_bfloat16* Bgs = Bg + sf * KSTAGE;
            uint32_t sAn = sA0 + nb * STAGE_BYTES;
            uint32_t sBn = sB0 + nb * STAGE_BYTES;
            CP_ASYNC16(sAn + ld_r0 * 80 + ld_c0 * 16, Ags + (size_t)ld_r0 * ND + ld_c0 * 8);
            CP_ASYNC16(sAn + ld_r1 * 80 + ld_c1 * 16, Ags + (size_t)ld_r1 * ND + ld_c1 * 8);
            CP_ASYNC16(sBn + ld_r0 * 80 + ld_c0 * 16, Bgs + (size_t)ld_r0 * ND + ld_c0 * 8);
            CP_ASYNC16(sBn + ld_r1 * 80 + ld_c1 * 16, Bgs + (size_t)ld_r1 * ND + ld_c1 * 8);
        }
        CP_COMMIT();

        uint32_t sAb = sA0 + buf * STAGE_BYTES;
        uint32_t sBb = sB0 + buf * STAGE_BYTES;
#pragma unroll
        for (int kk = 0; kk < 2; kk++) {
            uint32_t kbyte = kk * 32;
            uint32_t af[4][4], bf[2][4];
#pragma unroll
            for (int mt = 0; mt < 4; mt++)
                LDSM_X4(af[mt][0], af[mt][1], af[mt][2], af[mt][3],
                        sAb + aoff + mt * 16 * 80 + kbyte);
#pragma unroll
            for (int p = 0; p < 2; p++)
                LDSM_X4(bf[p][0], bf[p][1], bf[p][2], bf[p][3],
                        sBb + boff + p * 16 * 80 + kbyte);
#pragma unroll
            for (int mt = 0; mt < 4; mt++) {
#pragma unroll
                for (int nt = 0; nt < 4; nt++) {
                    int p = nt >> 1, h = (nt & 1) * 2;
                    MMA16816(acc[mt][nt], af[mt][0], af[mt][1], af[mt][2], af[mt][3],
                             bf[p][h], bf[p][h + 1]);
                }
            }
        }
    }

    // ---------- fused epilogue ----------
    __syncthreads();   // mainloop smem reads done; reuse as fp32 tile [128][132]
    float* st = (float*)smem;
    const float* bi = bias + nBase;
#pragma unroll
    for (int mt = 0; mt < 4; mt++) {
        int lr = wm + mt * 16 + (lane >> 2);
#pragma unroll
        for (int nt = 0; nt < 4; nt++) {
            int lc = wn + nt * 8 + (lane & 3) * 2;
            float b0 = bi[lc], b1 = bi[lc + 1];
            *(float2*)(st + lr * 132 + lc) =
                make_float2(acc[mt][nt][0] + b0, acc[mt][nt][1] + b1);
            *(float2*)(st + (lr + 8) * 132 + lc) =
                make_float2(acc[mt][nt][2] + b0, acc[mt][nt][3] + b1);
        }
    }
    __syncthreads();

    const int b = by >> 2;                       // batch element of this M block
    const int* tg = target + b * NL;
#pragma unroll 1
    for (int rr = 0; rr < 16; rr++) {
        int r = wid * 16 + rr;
        const float* row = st + r * 132;
        float4 v = ((const float4*)row)[lane];
        float m = fmaxf(fmaxf(v.x, v.y), fmaxf(v.z, v.w));
#pragma unroll
        for (int o = 16; o > 0; o >>= 1) m = fmaxf(m, __shfl_xor_sync(0xffffffffu, m, o));
        float se = __expf(v.x - m) + __expf(v.y - m) + __expf(v.z - m) + __expf(v.w - m);
#pragma unroll
        for (int o = 16; o > 0; o >>= 1) se += __shfl_xor_sync(0xffffffffu, se, o);

        size_t grow = (size_t)(mBase + r);
        if (lane == 0) g_part[grow * 8 + bx] = make_float2(m, se);

        // gather labels that live in this 128-wide slice
#pragma unroll
        for (int j0 = 0; j0 < NL; j0 += 32) {
            int j = j0 + lane;
            int lab = tg[j];
            if ((lab >> 7) == bx)
                g_gather[grow * GST + j + 1] = __expf(row[lab & 127] - m);
        }
        if (bx == 0 && lane == 0)
            g_gather[grow * GST] = __expf(row[0] - m);   // blank
    }
}

// ---------------------------------------------------------------------------
// Kernel 2: combine slice partials -> probabilities at extended labels
// ---------------------------------------------------------------------------
__global__ __launch_bounds__(256) void combine_kernel(const int* __restrict__ target) {
    int warp = threadIdx.x >> 5, lane = threadIdx.x & 31;
    int row = blockIdx.x * 8 + warp;
    int b = row >> 9;

    float2 ms = (lane < 8) ? g_part[(size_t)row * 8 + lane] : make_float2(-CUDART_INF_F, 0.f);
    float m = ms.x;
#pragma unroll
    for (int o = 16; o > 0; o >>= 1) m = fmaxf(m, __shfl_xor_sync(0xffffffffu, m, o));
    float rel = (lane < 8) ? __expf(ms.x - m) : 0.f;
    float tot = ms.y * rel;
#pragma unroll
    for (int o = 16; o > 0; o >>= 1) tot += __shfl_xor_sync(0xffffffffu, tot, o);
    float scale = rel / tot;    // valid for lane < 8

    const float* G = g_gather + (size_t)row * GST;
    float* P = g_pext + (size_t)row * SPAD;
    const int* tg = target + b * NL;

    float sc0 = __shfl_sync(0xffffffffu, scale, 0);
    float pblank = G[0] * sc0;   // broadcast load

#pragma unroll
    for (int j0 = 0; j0 < NL; j0 += 32) {
        int j = j0 + lane;
        int lab = tg[j];
        float sc = __shfl_sync(0xffffffffu, scale, lab >> 7);
        P[2 * j + 1] = G[j + 1] * sc;
    }
#pragma unroll
    for (int j0 = 0; j0 <= NL; j0 += 32) {
        int j = j0 + lane;
        if (j <= NL) P[2 * j] = pblank;
    }
    if (lane < 31) P[NS + lane] = 0.f;
}

// ---------------------------------------------------------------------------
// Kernel 3: CTC forward recursion, probability domain.
//   Rescale every 4 steps by an exact power of 2 (exponent trick, no MUFU).
//   Prefetch depth 7 (511 = 73*7).
// ---------------------------------------------------------------------------
#define CDEPTH 7

__global__ __launch_bounds__(32) void ctc_kernel(const int* __restrict__ target,
                                                 const int* __restrict__ in_len,
                                                 const int* __restrict__ tgt_len) {
    int b = blockIdx.x;
    int lane = threadIdx.x;
    int s0 = lane * 9;
    const int* tg = target + b * NL;

    unsigned skipm = 0;
#pragma unroll
    for (int k = 0; k < 9; k++) {
        int s = s0 + k;
        if (s >= 3 && s < NS && (s & 1)) {
            int j = (s - 1) >> 1;
            if (tg[j] != tg[j - 1]) skipm |= (1u << k);
        }
    }

    const float* P = g_pext + (size_t)b * NT * SPAD;
    int TL = in_len[b];
    int tl = tgt_len[b];
    int send1 = 2 * tl - 1, send2 = 2 * tl;

    float a[9];
#pragma unroll
    for (int k = 0; k < 9; k++) {
        int s = s0 + k;
        float p = (s < NS) ? P[s] : 0.f;
        a[k] = (s < 2) ? p : 0.f;
    }

    int escale = 0;            // true alpha = a * 2^escale
    float ll = -CUDART_INF_F;
    const float LN2 = 0.6931471805599453f;

    if (TL == 1) {
        float part = 0.f;
#pragma unroll
        for (int k = 0; k < 9; k++) {
            int s = s0 + k;
            part += (s == send1 || s == send2) ? a[k] : 0.f;
        }
#pragma unroll
        for (int o = 16; o > 0; o >>= 1) part += __shfl_xor_sync(0xffffffffu, part, o);
        ll = __logf(part);
    }

    float pf[CDEPTH][9];
#pragma unroll
    for (int u = 0; u < CDEPTH; u++) {
        const float* Pt = P + (size_t)(u + 1) * SPAD;
#pragma unroll
        for (int k = 0; k < 9; k++) { int s = s0 + k; pf[u][k] = (s < NS) ? Pt[s] : 0.f; }
    }

#pragma unroll 1
    for (int tb = 1; tb < NT; tb += CDEPTH) {
#pragma unroll
        for (int u = 0; u < CDEPTH; u++) {
            int t = tb + u;

            float up1 = __shfl_up_sync(0xffffffffu, a[8], 1);
            float up2 = __shfl_up_sync(0xffffffffu, a[7], 1);
            if (lane == 0) { up1 = 0.f; up2 = 0.f; }

            float na[9];
#pragma unroll
            for (int k = 0; k < 9; k++) {
                float sm1 = (k >= 1) ? a[k - 1] : up1;
                float sm2 = (k >= 2) ? a[k - 2] : ((k == 1) ? up1 : up2);
                float c = a[k] + sm1;
                if ((skipm >> k) & 1u) c += sm2;
                na[k] = c * pf[u][k];
            }
#pragma unroll
            for (int k = 0; k < 9; k++) a[k] = na[k];

            if (t == TL - 1) {
                float part = 0.f;
#pragma unroll
                for (int k = 0; k < 9; k++) {
                    int s = s0 + k;
                    part += (s == send1 || s == send2) ? a[k] : 0.f;
                }
#pragma unroll
                for (int o = 16; o > 0; o >>= 1) part += __shfl_xor_sync(0xffffffffu, part, o);
                ll = (float)escale * LN2 + __logf(part);
            }

            if ((t & 3) == 3) {
                float tot = 0.f;
#pragma unroll
                for (int k = 0; k < 9; k++) tot += a[k];
#pragma unroll
                for (int o = 16; o > 0; o >>= 1) tot += __shfl_xor_sync(0xffffffffu, tot, o);
                if (tot > 0.f) {
                    unsigned E = (__float_as_uint(tot) >> 23) & 0xffu;
                    float sc = __uint_as_float((254u - E) << 23);   // exact 2^(127-E)
                    escale += (int)E - 127;
#pragma unroll
                    for (int k = 0; k < 9; k++) a[k] *= sc;
                }
            }

            int tn = t + CDEPTH;
            if (tn < NT) {
                const float* Pt = P + (size_t)tn * SPAD;
#pragma unroll
                for (int k = 0; k < 9; k++) { int s = s0 + k; pf[u][k] = (s < NS) ? Pt[s] : 0.f; }
            } else {
#pragma unroll
                for (int k = 0; k < 9; k++) pf[u][k] = 0.f;
            }
        }
    }

    if (lane == 0) {
        float nll = -ll;
        if (!(nll < 1e29f)) nll = 0.f;
        g_loss[b] = nll / fmaxf((float)tl, 1.f);
    }
}

// ---------------------------------------------------------------------------
// Kernel 4: mean over batch
// ---------------------------------------------------------------------------
__global__ void reduce_kernel(float* __restrict__ out) {
    int lane = threadIdx.x;
    float v = (lane < NB) ? g_loss[lane] : 0.f;
#pragma unroll
    for (int o = 16; o > 0; o >>= 1) v += __shfl_xor_sync(0xffffffffu, v, o);
    if (lane == 0) out[0] = v * (1.f / NB);
}

extern "C" void kernel_launch(void* const* d_in, const int* in_sizes, int n_in,
                              void* d_out, int out_size) {
    const float* x = (const float*)d_in[0];        // [B,T,D]
    const float* W = (const float*)d_in[1];        // [D,V]
    const float* bias = (const float*)d_in[2];     // [V]
    const int* target = (const int*)d_in[3];       // [B,L]
    const int* in_len = (const int*)d_in[4];       // [B]
    const int* tgt_len = (const int*)d_in[5];      // [B]

    cudaFuncSetAttribute(gemm_hmma_kernel,
                         cudaFuncAttributeMaxDynamicSharedMemorySize, GEMM_SMEM);

    convert_x_kernel<<<(NM * ND) / 4 / 256, 256>>>(x);
    {
        dim3 blk(32, 8), grd(NV / 32, ND / 32);
        convert_w_kernel<<<grd, blk>>>(W);
    }
    {
        dim3 gg(NV / 128, NM / 128);
        gemm_hmma_kernel<<<gg, 256, GEMM_SMEM>>>(bias, target);
    }
    combine_kernel<<<NM / 8, 256>>>(target);
    ctc_kernel<<<NB, 32>>>(target, in_len, tgt_len);
    reduce_kernel<<<1, 32>>>((float*)d_out);
}

// round 8
// speedup vs baseline: 1.0351x; 1.0351x over previous
#include <cuda_runtime.h>
#include <cuda_bf16.h>
#include <math_constants.h>
#include <cstdint>

#define NB 32
#define NT 512
#define ND 512
#define NV 1024
#define NL 128
#define NS 257      // 2*NL+1
#define SPAD 288    // padded S stride
#define NM (NB*NT)  // 16384 rows

// Scratch (allocation-free per harness rules)
__device__ float g_logits[(size_t)NM * NV];          // 64 MB
__device__ float g_pext[(size_t)NM * SPAD];          // 18.9 MB
__device__ float g_loss[NB];
__device__ int   g_cnt;                              // ctc completion counter
__device__ __nv_bfloat16 g_xb[(size_t)NM * ND];      // 16 MB  (x in bf16)
__device__ __nv_bfloat16 g_wt[(size_t)NV * ND];      // 1 MB   (W^T bf16 [V][D])

// ---------------------------------------------------------------------------
// PTX helpers (portable: cp.async sm_80+, ldmatrix sm_75+, mma.bf16 sm_80+)
// ---------------------------------------------------------------------------
__device__ __forceinline__ uint32_t smem_u32(const void* p) {
    uint32_t a;
    asm("{ .reg .u64 t; cvta.to.shared.u64 t, %1; cvt.u32.u64 %0, t; }" : "=r"(a) : "l"(p));
    return a;
}
#define CP_ASYNC16(dst, src) \
    asm volatile("cp.async.cg.shared.global [%0], [%1], 16;" :: "r"(dst), "l"(src))
#define CP_COMMIT() asm volatile("cp.async.commit_group;" ::: "memory")
#define CP_WAIT2()  asm volatile("cp.async.wait_group 2;" ::: "memory")

#define LDSM_X4(r0, r1, r2, r3, addr) \
    asm volatile("ldmatrix.sync.aligned.m8n8.x4.shared.b16 {%0,%1,%2,%3}, [%4];" \
                 : "=r"(r0), "=r"(r1), "=r"(r2), "=r"(r3) : "r"(addr))

#define MMA16816(d, a0, a1, a2, a3, b0, b1) \
    asm volatile("mma.sync.aligned.m16n8k16.row.col.f32.bf16.bf16.f32 " \
                 "{%0,%1,%2,%3}, {%4,%5,%6,%7}, {%8,%9}, {%0,%1,%2,%3};" \
                 : "+f"((d)[0]), "+f"((d)[1]), "+f"((d)[2]), "+f"((d)[3]) \
                 : "r"(a0), "r"(a1), "r"(a2), "r"(a3), "r"(b0), "r"(b1))

// ---------------------------------------------------------------------------
// Convert x -> bf16
// ---------------------------------------------------------------------------
__global__ __launch_bounds__(256) void convert_x_kernel(const float* __restrict__ x) {
    size_t i = ((size_t)blockIdx.x * 256 + threadIdx.x) * 4;
    float4 v = *(const float4*)(x + i);
    __nv_bfloat162 a = __floats2bfloat162_rn(v.x, v.y);
    __nv_bfloat162 b = __floats2bfloat162_rn(v.z, v.w);
    *(__nv_bfloat162*)(g_xb + i) = a;
    *(__nv_bfloat162*)(g_xb + i + 2) = b;
}

// ---------------------------------------------------------------------------
// Convert + transpose W[D][V] fp32 -> g_wt[V][D] bf16
// ---------------------------------------------------------------------------
__global__ __launch_bounds__(256) void convert_w_kernel(const float* __restrict__ W) {
    __shared__ float t[32][33];
    int tx = threadIdx.x, ty = threadIdx.y;
    int n0 = blockIdx.x * 32, k0 = blockIdx.y * 32;
#pragma unroll
    for (int j = 0; j < 32; j += 8)
        t[ty + j][tx] = W[(size_t)(k0 + ty + j) * NV + n0 + tx];
    __syncthreads();
#pragma unroll
    for (int j = 0; j < 32; j += 8)
        g_wt[(size_t)(n0 + ty + j) * ND + k0 + tx] = __float2bfloat16(t[tx][ty + j]);
}

// ---------------------------------------------------------------------------
// Kernel 1: bf16 HMMA GEMM via mma.sync m16n8k16.
//   CTA tile 128x128, 8 warps (2x4), warp tile 64x32, K stages of 32,
//   cp.async 4-stage pipeline, occupancy 2 (launch bounds cap regs).
// ---------------------------------------------------------------------------
#define KSTAGE 32
#define SROW 40           // padded row stride in bf16 elems (80 bytes)
#define PSTAGES 4
#define STAGE_BYTES (128 * SROW * 2)            // 10240 B per tile
#define GEMM_SMEM (PSTAGES * STAGE_BYTES * 2)   // 81920 B total

__global__ __launch_bounds__(256, 2) void gemm_hmma_kernel(const float* __restrict__ bias) {
    extern __shared__ __align__(16) char smem[];

    const int tid = threadIdx.x, wid = tid >> 5, lane = tid & 31;
    const int bx = blockIdx.x;           // N tile (0..7)
    const int by = blockIdx.y;           // M tile (0..127)
    const int mBase = by * 128, nBase = bx * 128;
    const int wm = (wid >> 2) * 64;      // warp M offset in tile
    const int wn = (wid & 3) * 32;       // warp N offset in tile

    const __nv_bfloat16* Ag = g_xb + (size_t)mBase * ND;
    const __nv_bfloat16* Bg = g_wt + (size_t)nBase * ND;

    uint32_t sA0 = smem_u32(smem);
    uint32_t sB0 = sA0 + PSTAGES * STAGE_BYTES;

    const int ld_r0 = tid >> 2, ld_c0 = (tid & 3);
    const int ld_r1 = (tid + 256) >> 2, ld_c1 = ((tid + 256) & 3);

    const int NSTAGES = ND / KSTAGE;   // 16

#pragma unroll
    for (int s = 0; s < PSTAGES - 1; s++) {
        const __nv_bfloat16* Ags = Ag + s * KSTAGE;
        const __nv_bfloat16* Bgs = Bg + s * KSTAGE;
        uint32_t sAn = sA0 + s * STAGE_BYTES;
        uint32_t sBn = sB0 + s * STAGE_BYTES;
        CP_ASYNC16(sAn + ld_r0 * 80 + ld_c0 * 16, Ags + (size_t)ld_r0 * ND + ld_c0 * 8);
        CP_ASYNC16(sAn + ld_r1 * 80 + ld_c1 * 16, Ags + (size_t)ld_r1 * ND + ld_c1 * 8);
        CP_ASYNC16(sBn + ld_r0 * 80 + ld_c0 * 16, Bgs + (size_t)ld_r0 * ND + ld_c0 * 8);
        CP_ASYNC16(sBn + ld_r1 * 80 + ld_c1 * 16, Bgs + (size_t)ld_r1 * ND + ld_c1 * 8);
        CP_COMMIT();
    }

    float acc[4][4][4];
#pragma unroll
    for (int i = 0; i < 4; i++)
#pragma unroll
        for (int j = 0; j < 4; j++)
#pragma unroll
            for (int r = 0; r < 4; r++) acc[i][j][r] = 0.f;

    uint32_t aoff = (uint32_t)((wm + (lane & 15)) * 80 + (lane >> 4) * 16);
    uint32_t boff = (uint32_t)((wn + ((lane >> 4) & 1) * 8 + (lane & 7)) * 80 +
                               ((lane >> 3) & 1) * 16);

#pragma unroll 1
    for (int ks = 0; ks < NSTAGES; ks++) {
        int buf = ks & (PSTAGES - 1);
        CP_WAIT2();             // stage ks data arrived
        __syncthreads();        // readers of recycled buffer are done

        int sf = ks + PSTAGES - 1;
        if (sf < NSTAGES) {
            int nb = sf & (PSTAGES - 1);
            const __nv_bfloat16* Ags = Ag + sf * KSTAGE;
            const __nv_bfloat16* Bgs = Bg + sf * KSTAGE;
            uint32_t sAn = sA0 + nb * STAGE_BYTES;
            uint32_t sBn = sB0 + nb * STAGE_BYTES;
            CP_ASYNC16(sAn + ld_r0 * 80 + ld_c0 * 16, Ags + (size_t)ld_r0 * ND + ld_c0 * 8);
            CP_ASYNC16(sAn + ld_r1 * 80 + ld_c1 * 16, Ags + (size_t)ld_r1 * ND + ld_c1 * 8);
            CP_ASYNC16(sBn + ld_r0 * 80 + ld_c0 * 16, Bgs + (size_t)ld_r0 * ND + ld_c0 * 8);
            CP_ASYNC16(sBn + ld_r1 * 80 + ld_c1 * 16, Bgs + (size_t)ld_r1 * ND + ld_c1 * 8);
        }
        CP_COMMIT();

        uint32_t sAb = sA0 + buf * STAGE_BYTES;
        uint32_t sBb = sB0 + buf * STAGE_BYTES;
#pragma unroll
        for (int kk = 0; kk < 2; kk++) {
            uint32_t kbyte = kk * 32;
            uint32_t af[4][4], bf[2][4];
#pragma unroll
            for (int mt = 0; mt < 4; mt++)
                LDSM_X4(af[mt][0], af[mt][1], af[mt][2], af[mt][3],
                        sAb + aoff + mt * 16 * 80 + kbyte);
#pragma unroll
            for (int p = 0; p < 2; p++)
                LDSM_X4(bf[p][0], bf[p][1], bf[p][2], bf[p][3],
                        sBb + boff + p * 16 * 80 + kbyte);
#pragma unroll
            for (int mt = 0; mt < 4; mt++) {
#pragma unroll
                for (int nt = 0; nt < 4; nt++) {
                    int p = nt >> 1, h = (nt & 1) * 2;
                    MMA16816(acc[mt][nt], af[mt][0], af[mt][1], af[mt][2], af[mt][3],
                             bf[p][h], bf[p][h + 1]);
                }
            }
        }
    }

    // epilogue: +bias, store fp32 logits
    const float* bi = bias + nBase + wn;
#pragma unroll
    for (int mt = 0; mt < 4; mt++) {
        int r0 = mBase + wm + mt * 16 + (lane >> 2);
#pragma unroll
        for (int nt = 0; nt < 4; nt++) {
            int c = nt * 8 + (lane & 3) * 2;
            float b0 = bi[c], b1 = bi[c + 1];
            float2 v0 = make_float2(acc[mt][nt][0] + b0, acc[mt][nt][1] + b1);
            float2 v1 = make_float2(acc[mt][nt][2] + b0, acc[mt][nt][3] + b1);
            *(float2*)(g_logits + (size_t)r0 * NV + nBase + wn + c) = v0;
            *(float2*)(g_logits + (size_t)(r0 + 8) * NV + nBase + wn + c) = v1;
        }
    }
}

// ---------------------------------------------------------------------------
// Kernel 2: per-row softmax over V, emit PROBABILITIES at extended labels
// ---------------------------------------------------------------------------
__global__ __launch_bounds__(256) void softmax_kernel(const int* __restrict__ target) {
    int warp = threadIdx.x >> 5, lane = threadIdx.x & 31;
    int row = blockIdx.x * 8 + warp;
    int b = row >> 9;
    const float* lg = g_logits + (size_t)row * NV;

    float m = -CUDART_INF_F;
    float4 v[8];
#pragma unroll
    for (int i = 0; i < 8; i++) {
        v[i] = *(const float4*)(lg + i * 128 + lane * 4);
        m = fmaxf(m, fmaxf(fmaxf(v[i].x, v[i].y), fmaxf(v[i].z, v[i].w)));
    }
#pragma unroll
    for (int o = 16; o > 0; o >>= 1) m = fmaxf(m, __shfl_xor_sync(0xffffffffu, m, o));

    float se = 0.f;
#pragma unroll
    for (int i = 0; i < 8; i++)
        se += __expf(v[i].x - m) + __expf(v[i].y - m) + __expf(v[i].z - m) + __expf(v[i].w - m);
#pragma unroll
    for (int o = 16; o > 0; o >>= 1) se += __shfl_xor_sync(0xffffffffu, se, o);

    float inv = 1.f / se;
    float pblank = __expf(lg[0] - m) * inv;

    float* P = g_pext + (size_t)row * SPAD;
    const int* tg = target + b * NL;
    for (int j = lane; j < NL; j += 32) {
        int lab = tg[j];
        P[2 * j + 1] = __expf(lg[lab] - m) * inv;
    }
    for (int j = lane; j <= NL; j += 32) P[2 * j] = pblank;
    if (lane < 31) P[NS + lane] = 0.f;
}

// ---------------------------------------------------------------------------
// Kernel 3: CTC forward recursion, probability domain.
//   Rescale every 4 steps by an exact power of 2 (exponent trick, no MUFU).
//   Prefetch depth 7 (511 = 73*7). Final mean fused via atomic counter.
// ---------------------------------------------------------------------------
#define CDEPTH 7

__global__ __launch_bounds__(32) void ctc_kernel(const int* __restrict__ target,
                                                 const int* __restrict__ in_len,
                                                 const int* __restrict__ tgt_len,
                                                 float* __restrict__ out) {
    int b = blockIdx.x;
    int lane = threadIdx.x;
    int s0 = lane * 9;
    const int* tg = target + b * NL;

    unsigned skipm = 0;
#pragma unroll
    for (int k = 0; k < 9; k++) {
        int s = s0 + k;
        if (s >= 3 && s < NS && (s & 1)) {
            int j = (s - 1) >> 1;
            if (tg[j] != tg[j - 1]) skipm |= (1u << k);
        }
    }

    const float* P = g_pext + (size_t)b * NT * SPAD;
    int TL = in_len[b];
    int tl = tgt_len[b];
    int send1 = 2 * tl - 1, send2 = 2 * tl;

    float a[9];
#pragma unroll
    for (int k = 0; k < 9; k++) {
        int s = s0 + k;
        float p = (s < NS) ? P[s] : 0.f;
        a[k] = (s < 2) ? p : 0.f;
    }

    int escale = 0;            // true alpha = a * 2^escale
    float ll = -CUDART_INF_F;
    const float LN2 = 0.6931471805599453f;

    if (TL == 1) {
        float part = 0.f;
#pragma unroll
        for (int k = 0; k < 9; k++) {
            int s = s0 + k;
            part += (s == send1 || s == send2) ? a[k] : 0.f;
        }
#pragma unroll
        for (int o = 16; o > 0; o >>= 1) part += __shfl_xor_sync(0xffffffffu, part, o);
        ll = __logf(part);
    }

    float pf[CDEPTH][9];
#pragma unroll
    for (int u = 0; u < CDEPTH; u++) {
        const float* Pt = P + (size_t)(u + 1) * SPAD;
#pragma unroll
        for (int k = 0; k < 9; k++) { int s = s0 + k; pf[u][k] = (s < NS) ? Pt[s] : 0.f; }
    }

#pragma unroll 1
    for (int tb = 1; tb < NT; tb += CDEPTH) {
#pragma unroll
        for (int u = 0; u < CDEPTH; u++) {
            int t = tb + u;

            float up1 = __shfl_up_sync(0xffffffffu, a[8], 1);
            float up2 = __shfl_up_sync(0xffffffffu, a[7], 1);
            if (lane == 0) { up1 = 0.f; up2 = 0.f; }

            float na[9];
#pragma unroll
            for (int k = 0; k < 9; k++) {
                float sm1 = (k >= 1) ? a[k - 1] : up1;
                float sm2 = (k >= 2) ? a[k - 2] : ((k == 1) ? up1 : up2);
                float c = a[k] + sm1;
                if ((skipm >> k) & 1u) c += sm2;
                na[k] = c * pf[u][k];
            }
#pragma unroll
            for (int k = 0; k < 9; k++) a[k] = na[k];

            if (t == TL - 1) {
                float part = 0.f;
#pragma unroll
                for (int k = 0; k < 9; k++) {
                    int s = s0 + k;
                    part += (s == send1 || s == send2) ? a[k] : 0.f;
                }
#pragma unroll
                for (int o = 16; o > 0; o >>= 1) part += __shfl_xor_sync(0xffffffffu, part, o);
                ll = (float)escale * LN2 + __logf(part);
            }

            if ((t & 3) == 3) {
                float tot = 0.f;
#pragma unroll
                for (int k = 0; k < 9; k++) tot += a[k];
#pragma unroll
                for (int o = 16; o > 0; o >>= 1) tot += __shfl_xor_sync(0xffffffffu, tot, o);
                if (tot > 0.f) {
                    unsigned E = (__float_as_uint(tot) >> 23) & 0xffu;
                    float sc = __uint_as_float((254u - E) << 23);   // exact 2^(127-E)
                    escale += (int)E - 127;
#pragma unroll
                    for (int k = 0; k < 9; k++) a[k] *= sc;
                }
            }

            int tn = t + CDEPTH;
            if (tn < NT) {
                const float* Pt = P + (size_t)tn * SPAD;
#pragma unroll
                for (int k = 0; k < 9; k++) { int s = s0 + k; pf[u][k] = (s < NS) ? Pt[s] : 0.f; }
            } else {
#pragma unroll
                for (int k = 0; k < 9; k++) pf[u][k] = 0.f;
            }
        }
    }

    if (lane == 0) {
        float nll = -ll;
        if (!(nll < 1e29f)) nll = 0.f;
        g_loss[b] = nll / fmaxf((float)tl, 1.f);
        __threadfence();
        int prev = atomicAdd(&g_cnt, 1);
        if (prev == NB - 1) {
            float s = 0.f;
#pragma unroll
            for (int i = 0; i < NB; i++) s += g_loss[i];
            out[0] = s * (1.f / NB);
            g_cnt = 0;   // reset for next graph replay (deterministic)
        }
    }
}

extern "C" void kernel_launch(void* const* d_in, const int* in_sizes, int n_in,
                              void* d_out, int out_size) {
    const float* x = (const float*)d_in[0];        // [B,T,D]
    const float* W = (const float*)d_in[1];        // [D,V]
    const float* bias = (const float*)d_in[2];     // [V]
    const int* target = (const int*)d_in[3];       // [B,L]
    const int* in_len = (const int*)d_in[4];       // [B]
    const int* tgt_len = (const int*)d_in[5];      // [B]

    cudaFuncSetAttribute(gemm_hmma_kernel,
                         cudaFuncAttributeMaxDynamicSharedMemorySize, GEMM_SMEM);

    convert_x_kernel<<<(NM * ND) / 4 / 256, 256>>>(x);
    {
        dim3 blk(32, 8), grd(NV / 32, ND / 32);
        convert_w_kernel<<<grd, blk>>>(W);
    }
    {
        dim3 gg(NV / 128, NM / 128);
        gemm_hmma_kernel<<<gg, 256, GEMM_SMEM>>>(bias);
    }
    softmax_kernel<<<NM / 8, 256>>>(target);
    ctc_kernel<<<NB, 32>>>(target, in_len, tgt_len, (float*)d_out);
}

// round 9
// speedup vs baseline: 1.0796x; 1.0430x over previous
#include <cuda_runtime.h>
#include <cuda_bf16.h>
#include <math_constants.h>
#include <cstdint>

#define NB 32
#define NT 512
#define ND 512
#define NV 1024
#define NL 128
#define NS 257      // 2*NL+1
#define SPAD 288    // padded S stride
#define NM (NB*NT)  // 16384 rows

// Scratch (allocation-free per harness rules)
__device__ float g_logits[(size_t)NM * NV];          // 64 MB
__device__ float g_pext[(size_t)NM * SPAD];          // 18.9 MB
__device__ float g_loss[NB];
__device__ int   g_cnt;                              // ctc completion counter
__device__ __nv_bfloat16 g_xb[(size_t)NM * ND];      // 16 MB  (x in bf16)
__device__ __nv_bfloat16 g_wt[(size_t)NV * ND];      // 1 MB   (W^T bf16 [V][D])

// ---------------------------------------------------------------------------
// PTX helpers (portable: cp.async sm_80+, ldmatrix sm_75+, mma.bf16 sm_80+)
// ---------------------------------------------------------------------------
__device__ __forceinline__ uint32_t smem_u32(const void* p) {
    uint32_t a;
    asm("{ .reg .u64 t; cvta.to.shared.u64 t, %1; cvt.u32.u64 %0, t; }" : "=r"(a) : "l"(p));
    return a;
}
#define CP_ASYNC16(dst, src) \
    asm volatile("cp.async.cg.shared.global [%0], [%1], 16;" :: "r"(dst), "l"(src))
#define CP_COMMIT() asm volatile("cp.async.commit_group;" ::: "memory")
#define CP_WAIT1()  asm volatile("cp.async.wait_group 1;" ::: "memory")

#define LDSM_X4(r0, r1, r2, r3, addr) \
    asm volatile("ldmatrix.sync.aligned.m8n8.x4.shared.b16 {%0,%1,%2,%3}, [%4];" \
                 : "=r"(r0), "=r"(r1), "=r"(r2), "=r"(r3) : "r"(addr))

#define MMA16816(d, a0, a1, a2, a3, b0, b1) \
    asm volatile("mma.sync.aligned.m16n8k16.row.col.f32.bf16.bf16.f32 " \
                 "{%0,%1,%2,%3}, {%4,%5,%6,%7}, {%8,%9}, {%0,%1,%2,%3};" \
                 : "+f"((d)[0]), "+f"((d)[1]), "+f"((d)[2]), "+f"((d)[3]) \
                 : "r"(a0), "r"(a1), "r"(a2), "r"(a3), "r"(b0), "r"(b1))

// ---------------------------------------------------------------------------
// Convert x -> bf16
// ---------------------------------------------------------------------------
__global__ __launch_bounds__(256) void convert_x_kernel(const float* __restrict__ x) {
    size_t i = ((size_t)blockIdx.x * 256 + threadIdx.x) * 4;
    float4 v = *(const float4*)(x + i);
    __nv_bfloat162 a = __floats2bfloat162_rn(v.x, v.y);
    __nv_bfloat162 b = __floats2bfloat162_rn(v.z, v.w);
    *(__nv_bfloat162*)(g_xb + i) = a;
    *(__nv_bfloat162*)(g_xb + i + 2) = b;
}

// ---------------------------------------------------------------------------
// Convert + transpose W[D][V] fp32 -> g_wt[V][D] bf16
// ---------------------------------------------------------------------------
__global__ __launch_bounds__(256) void convert_w_kernel(const float* __restrict__ W) {
    __shared__ float t[32][33];
    int tx = threadIdx.x, ty = threadIdx.y;
    int n0 = blockIdx.x * 32, k0 = blockIdx.y * 32;
#pragma unroll
    for (int j = 0; j < 32; j += 8)
        t[ty + j][tx] = W[(size_t)(k0 + ty + j) * NV + n0 + tx];
    __syncthreads();
#pragma unroll
    for (int j = 0; j < 32; j += 8)
        g_wt[(size_t)(n0 + ty + j) * ND + k0 + tx] = __float2bfloat16(t[tx][ty + j]);
}

// ---------------------------------------------------------------------------
// Kernel 1: bf16 HMMA GEMM via mma.sync m16n8k16.
//   CTA tile 128x128, 8 warps (2x4), warp tile 64x32.
//   K stages of 64 (8 stages total), 3-deep cp.async pipeline -> only 8
//   stage boundaries (syncs) and one full stage of prefetch cover.
//   smem row stride 144 B: ldmatrix phases hit banks 4r (conflict-free),
//   cp.async quarter-warp phases cover all 32 banks (conflict-free).
// ---------------------------------------------------------------------------
#define KSTAGE 64
#define SROWB 144          // row stride in bytes (128 data + 16 pad)
#define PSTAGES 3
#define STAGE_BYTES (128 * SROWB)               // 18432 B per tile
#define GEMM_SMEM (PSTAGES * STAGE_BYTES * 2)   // 110592 B total

__global__ __launch_bounds__(256) void gemm_hmma_kernel(const float* __restrict__ bias) {
    extern __shared__ __align__(16) char smem[];

    const int tid = threadIdx.x, wid = tid >> 5, lane = tid & 31;
    const int bx = blockIdx.x;           // N tile (0..7)
    const int by = blockIdx.y;           // M tile (0..127)
    const int mBase = by * 128, nBase = bx * 128;
    const int wm = (wid >> 2) * 64;      // warp M offset in tile
    const int wn = (wid & 3) * 32;       // warp N offset in tile

    const __nv_bfloat16* Ag = g_xb + (size_t)mBase * ND;
    const __nv_bfloat16* Bg = g_wt + (size_t)nBase * ND;

    uint32_t sA0 = smem_u32(smem);
    uint32_t sB0 = sA0 + PSTAGES * STAGE_BYTES;

    // cp.async slots: 1024 chunks of 16B per matrix per stage; 4 per thread.
    // idx = tid + j*256 ; row = idx>>3 ; chunk = idx&7
    const int NSTG = ND / KSTAGE;   // 8

    // prologue: stages 0,1
#pragma unroll
    for (int s = 0; s < PSTAGES - 1; s++) {
        const __nv_bfloat16* Ags = Ag + s * KSTAGE;
        const __nv_bfloat16* Bgs = Bg + s * KSTAGE;
        uint32_t sAn = sA0 + s * STAGE_BYTES;
        uint32_t sBn = sB0 + s * STAGE_BYTES;
#pragma unroll
        for (int j = 0; j < 4; j++) {
            int idx = tid + j * 256;
            int r = idx >> 3, c = idx & 7;
            CP_ASYNC16(sAn + r * SROWB + c * 16, Ags + (size_t)r * ND + c * 8);
            CP_ASYNC16(sBn + r * SROWB + c * 16, Bgs + (size_t)r * ND + c * 8);
        }
        CP_COMMIT();
    }

    float acc[4][4][4];
#pragma unroll
    for (int i = 0; i < 4; i++)
#pragma unroll
        for (int j = 0; j < 4; j++)
#pragma unroll
            for (int r = 0; r < 4; r++) acc[i][j][r] = 0.f;

    // ldmatrix lane address offsets (within a stage, kk=0)
    uint32_t aoff = (uint32_t)((wm + (lane & 15)) * SROWB + (lane >> 4) * 16);
    uint32_t boff = (uint32_t)((wn + ((lane >> 4) & 1) * 8 + (lane & 7)) * SROWB +
                               ((lane >> 3) & 1) * 16);

#pragma unroll 1
    for (int ks = 0; ks < NSTG; ks++) {
        int buf = ks % PSTAGES;
        CP_WAIT1();             // stage ks arrived (only stage ks+1 may be pending)
        __syncthreads();        // all warps done reading the buffer being recycled

        int sf = ks + PSTAGES - 1;      // stage to prefetch
        if (sf < NSTG) {
            int nb = sf % PSTAGES;
            const __nv_bfloat16* Ags = Ag + sf * KSTAGE;
            const __nv_bfloat16* Bgs = Bg + sf * KSTAGE;
            uint32_t sAn = sA0 + nb * STAGE_BYTES;
            uint32_t sBn = sB0 + nb * STAGE_BYTES;
#pragma unroll
            for (int j = 0; j < 4; j++) {
                int idx = tid + j * 256;
                int r = idx >> 3, c = idx & 7;
                CP_ASYNC16(sAn + r * SROWB + c * 16, Ags + (size_t)r * ND + c * 8);
                CP_ASYNC16(sBn + r * SROWB + c * 16, Bgs + (size_t)r * ND + c * 8);
            }
        }
        CP_COMMIT();            // one group per iteration (may be empty)

        uint32_t sAb = sA0 + buf * STAGE_BYTES;
        uint32_t sBb = sB0 + buf * STAGE_BYTES;
#pragma unroll
        for (int kk = 0; kk < 4; kk++) {   // four k16 sub-steps per 64-K stage
            uint32_t kbyte = kk * 32;
            uint32_t af[4][4], bf[2][4];
#pragma unroll
            for (int mt = 0; mt < 4; mt++)
                LDSM_X4(af[mt][0], af[mt][1], af[mt][2], af[mt][3],
                        sAb + aoff + mt * 16 * SROWB + kbyte);
#pragma unroll
            for (int p = 0; p < 2; p++)
                LDSM_X4(bf[p][0], bf[p][1], bf[p][2], bf[p][3],
                        sBb + boff + p * 16 * SROWB + kbyte);
#pragma unroll
            for (int mt = 0; mt < 4; mt++) {
#pragma unroll
                for (int nt = 0; nt < 4; nt++) {
                    int p = nt >> 1, h = (nt & 1) * 2;
                    MMA16816(acc[mt][nt], af[mt][0], af[mt][1], af[mt][2], af[mt][3],
                             bf[p][h], bf[p][h + 1]);
                }
            }
        }
    }

    // epilogue: +bias, store fp32 logits
    const float* bi = bias + nBase + wn;
#pragma unroll
    for (int mt = 0; mt < 4; mt++) {
        int r0 = mBase + wm + mt * 16 + (lane >> 2);
#pragma unroll
        for (int nt = 0; nt < 4; nt++) {
            int c = nt * 8 + (lane & 3) * 2;
            float b0 = bi[c], b1 = bi[c + 1];
            float2 v0 = make_float2(acc[mt][nt][0] + b0, acc[mt][nt][1] + b1);
            float2 v1 = make_float2(acc[mt][nt][2] + b0, acc[mt][nt][3] + b1);
            *(float2*)(g_logits + (size_t)r0 * NV + nBase + wn + c) = v0;
            *(float2*)(g_logits + (size_t)(r0 + 8) * NV + nBase + wn + c) = v1;
        }
    }
}

// ---------------------------------------------------------------------------
// Kernel 2: per-row softmax over V, emit PROBABILITIES at extended labels
// ---------------------------------------------------------------------------
__global__ __launch_bounds__(256) void softmax_kernel(const int* __restrict__ target) {
    int warp = threadIdx.x >> 5, lane = threadIdx.x & 31;
    int row = blockIdx.x * 8 + warp;
    int b = row >> 9;
    const float* lg = g_logits + (size_t)row * NV;

    float m = -CUDART_INF_F;
    float4 v[8];
#pragma unroll
    for (int i = 0; i < 8; i++) {
        v[i] = *(const float4*)(lg + i * 128 + lane * 4);
        m = fmaxf(m, fmaxf(fmaxf(v[i].x, v[i].y), fmaxf(v[i].z, v[i].w)));
    }
#pragma unroll
    for (int o = 16; o > 0; o >>= 1) m = fmaxf(m, __shfl_xor_sync(0xffffffffu, m, o));

    float se = 0.f;
#pragma unroll
    for (int i = 0; i < 8; i++)
        se += __expf(v[i].x - m) + __expf(v[i].y - m) + __expf(v[i].z - m) + __expf(v[i].w - m);
#pragma unroll
    for (int o = 16; o > 0; o >>= 1) se += __shfl_xor_sync(0xffffffffu, se, o);

    float inv = 1.f / se;
    float pblank = __expf(lg[0] - m) * inv;

    float* P = g_pext + (size_t)row * SPAD;
    const int* tg = target + b * NL;
    for (int j = lane; j < NL; j += 32) {
        int lab = tg[j];
        P[2 * j + 1] = __expf(lg[lab] - m) * inv;
    }
    for (int j = lane; j <= NL; j += 32) P[2 * j] = pblank;
    if (lane < 31) P[NS + lane] = 0.f;
}

// ---------------------------------------------------------------------------
// Kernel 3: CTC forward recursion, probability domain.
//   Rescale every 4 steps by an exact power of 2 (exponent trick, no MUFU).
//   Prefetch depth 7 (511 = 73*7). Final mean fused via atomic counter.
// ---------------------------------------------------------------------------
#define CDEPTH 7

__global__ __launch_bounds__(32) void ctc_kernel(const int* __restrict__ target,
                                                 const int* __restrict__ in_len,
                                                 const int* __restrict__ tgt_len,
                                                 float* __restrict__ out) {
    int b = blockIdx.x;
    int lane = threadIdx.x;
    int s0 = lane * 9;
    const int* tg = target + b * NL;

    unsigned skipm = 0;
#pragma unroll
    for (int k = 0; k < 9; k++) {
        int s = s0 + k;
        if (s >= 3 && s < NS && (s & 1)) {
            int j = (s - 1) >> 1;
            if (tg[j] != tg[j - 1]) skipm |= (1u << k);
        }
    }

    const float* P = g_pext + (size_t)b * NT * SPAD;
    int TL = in_len[b];
    int tl = tgt_len[b];
    int send1 = 2 * tl - 1, send2 = 2 * tl;

    float a[9];
#pragma unroll
    for (int k = 0; k < 9; k++) {
        int s = s0 + k;
        float p = (s < NS) ? P[s] : 0.f;
        a[k] = (s < 2) ? p : 0.f;
    }

    int escale = 0;            // true alpha = a * 2^escale
    float ll = -CUDART_INF_F;
    const float LN2 = 0.6931471805599453f;

    if (TL == 1) {
        float part = 0.f;
#pragma unroll
        for (int k = 0; k < 9; k++) {
            int s = s0 + k;
            part += (s == send1 || s == send2) ? a[k] : 0.f;
        }
#pragma unroll
        for (int o = 16; o > 0; o >>= 1) part += __shfl_xor_sync(0xffffffffu, part, o);
        ll = __logf(part);
    }

    float pf[CDEPTH][9];
#pragma unroll
    for (int u = 0; u < CDEPTH; u++) {
        const float* Pt = P + (size_t)(u + 1) * SPAD;
#pragma unroll
        for (int k = 0; k < 9; k++) { int s = s0 + k; pf[u][k] = (s < NS) ? Pt[s] : 0.f; }
    }

#pragma unroll 1
    for (int tb = 1; tb < NT; tb += CDEPTH) {
#pragma unroll
        for (int u = 0; u < CDEPTH; u++) {
            int t = tb + u;

            float up1 = __shfl_up_sync(0xffffffffu, a[8], 1);
            float up2 = __shfl_up_sync(0xffffffffu, a[7], 1);
            if (lane == 0) { up1 = 0.f; up2 = 0.f; }

            float na[9];
#pragma unroll
            for (int k = 0; k < 9; k++) {
                float sm1 = (k >= 1) ? a[k - 1] : up1;
                float sm2 = (k >= 2) ? a[k - 2] : ((k == 1) ? up1 : up2);
                float c = a[k] + sm1;
                if ((skipm >> k) & 1u) c += sm2;
                na[k] = c * pf[u][k];
            }
#pragma unroll
            for (int k = 0; k < 9; k++) a[k] = na[k];

            if (t == TL - 1) {
                float part = 0.f;
#pragma unroll
                for (int k = 0; k < 9; k++) {
                    int s = s0 + k;
                    part += (s == send1 || s == send2) ? a[k] : 0.f;
                }
#pragma unroll
                for (int o = 16; o > 0; o >>= 1) part += __shfl_xor_sync(0xffffffffu, part, o);
                ll = (float)escale * LN2 + __logf(part);
            }

            if ((t & 3) == 3) {
                float tot = 0.f;
#pragma unroll
                for (int k = 0; k < 9; k++) tot += a[k];
#pragma unroll
                for (int o = 16; o > 0; o >>= 1) tot += __shfl_xor_sync(0xffffffffu, tot, o);
                if (tot > 0.f) {
                    unsigned E = (__float_as_uint(tot) >> 23) & 0xffu;
                    float sc = __uint_as_float((254u - E) << 23);   // exact 2^(127-E)
                    escale += (int)E - 127;
#pragma unroll
                    for (int k = 0; k < 9; k++) a[k] *= sc;
                }
            }

            int tn = t + CDEPTH;
            if (tn < NT) {
                const float* Pt = P + (size_t)tn * SPAD;
#pragma unroll
                for (int k = 0; k < 9; k++) { int s = s0 + k; pf[u][k] = (s < NS) ? Pt[s] : 0.f; }
            } else {
#pragma unroll
                for (int k = 0; k < 9; k++) pf[u][k] = 0.f;
            }
        }
    }

    if (lane == 0) {
        float nll = -ll;
        if (!(nll < 1e29f)) nll = 0.f;
        g_loss[b] = nll / fmaxf((float)tl, 1.f);
        __threadfence();
        int prev = atomicAdd(&g_cnt, 1);
        if (prev == NB - 1) {
            float s = 0.f;
#pragma unroll
            for (int i = 0; i < NB; i++) s += g_loss[i];
            out[0] = s * (1.f / NB);
            g_cnt = 0;   // reset for next graph replay (deterministic)
        }
    }
}

extern "C" void kernel_launch(void* const* d_in, const int* in_sizes, int n_in,
                              void* d_out, int out_size) {
    const float* x = (const float*)d_in[0];        // [B,T,D]
    const float* W = (const float*)d_in[1];        // [D,V]
    const float* bias = (const float*)d_in[2];     // [V]
    const int* target = (const int*)d_in[3];       // [B,L]
    const int* in_len = (const int*)d_in[4];       // [B]
    const int* tgt_len = (const int*)d_in[5];      // [B]

    cudaFuncSetAttribute(gemm_hmma_kernel,
                         cudaFuncAttributeMaxDynamicSharedMemorySize, GEMM_SMEM);

    convert_x_kernel<<<(NM * ND) / 4 / 256, 256>>>(x);
    {
        dim3 blk(32, 8), grd(NV / 32, ND / 32);
        convert_w_kernel<<<grd, blk>>>(W);
    }
    {
        dim3 gg(NV / 128, NM / 128);
        gemm_hmma_kernel<<<gg, 256, GEMM_SMEM>>>(bias);
    }
    softmax_kernel<<<NM / 8, 256>>>(target);
    ctc_kernel<<<NB, 32>>>(target, in_len, tgt_len, (float*)d_out);
}

// round 10
// speedup vs baseline: 1.1590x; 1.0736x over previous
#include <cuda_runtime.h>
#include <cuda_bf16.h>
#include <math_constants.h>
#include <cstdint>

#define NB 32
#define NT 512
#define ND 512
#define NV 1024
#define NL 128
#define NS 257      // 2*NL+1
#define PROW 132    // compact row: [pblank, podd[0..127], 0, 0, 0]
#define NM (NB*NT)  // 16384 rows

// Scratch (allocation-free per harness rules)
__device__ float g_logits[(size_t)NM * NV];          // 64 MB
__device__ float g_pc[(size_t)NM * PROW];            // 8.6 MB compact probs
__device__ float g_loss[NB];
__device__ int   g_cnt;                              // ctc completion counter
__device__ __nv_bfloat16 g_xb[(size_t)NM * ND];      // 16 MB  (x in bf16)
__device__ __nv_bfloat16 g_wt[(size_t)NV * ND];      // 1 MB   (W^T bf16 [V][D])

// ---------------------------------------------------------------------------
// PTX helpers (portable: cp.async sm_80+, ldmatrix sm_75+, mma.bf16 sm_80+)
// ---------------------------------------------------------------------------
__device__ __forceinline__ uint32_t smem_u32(const void* p) {
    uint32_t a;
    asm("{ .reg .u64 t; cvta.to.shared.u64 t, %1; cvt.u32.u64 %0, t; }" : "=r"(a) : "l"(p));
    return a;
}
#define CP_ASYNC16(dst, src) \
    asm volatile("cp.async.cg.shared.global [%0], [%1], 16;" :: "r"(dst), "l"(src))
#define CP_COMMIT() asm volatile("cp.async.commit_group;" ::: "memory")
#define CP_WAIT1()  asm volatile("cp.async.wait_group 1;" ::: "memory")

#define LDSM_X4(r0, r1, r2, r3, addr) \
    asm volatile("ldmatrix.sync.aligned.m8n8.x4.shared.b16 {%0,%1,%2,%3}, [%4];" \
                 : "=r"(r0), "=r"(r1), "=r"(r2), "=r"(r3) : "r"(addr))

#define MMA16816(d, a0, a1, a2, a3, b0, b1) \
    asm volatile("mma.sync.aligned.m16n8k16.row.col.f32.bf16.bf16.f32 " \
                 "{%0,%1,%2,%3}, {%4,%5,%6,%7}, {%8,%9}, {%0,%1,%2,%3};" \
                 : "+f"((d)[0]), "+f"((d)[1]), "+f"((d)[2]), "+f"((d)[3]) \
                 : "r"(a0), "r"(a1), "r"(a2), "r"(a3), "r"(b0), "r"(b1))

// ---------------------------------------------------------------------------
// Convert x -> bf16
// ---------------------------------------------------------------------------
__global__ __launch_bounds__(256) void convert_x_kernel(const float* __restrict__ x) {
    size_t i = ((size_t)blockIdx.x * 256 + threadIdx.x) * 4;
    float4 v = *(const float4*)(x + i);
    __nv_bfloat162 a = __floats2bfloat162_rn(v.x, v.y);
    __nv_bfloat162 b = __floats2bfloat162_rn(v.z, v.w);
    *(__nv_bfloat162*)(g_xb + i) = a;
    *(__nv_bfloat162*)(g_xb + i + 2) = b;
}

// ---------------------------------------------------------------------------
// Convert + transpose W[D][V] fp32 -> g_wt[V][D] bf16
// ---------------------------------------------------------------------------
__global__ __launch_bounds__(256) void convert_w_kernel(const float* __restrict__ W) {
    __shared__ float t[32][33];
    int tx = threadIdx.x, ty = threadIdx.y;
    int n0 = blockIdx.x * 32, k0 = blockIdx.y * 32;
#pragma unroll
    for (int j = 0; j < 32; j += 8)
        t[ty + j][tx] = W[(size_t)(k0 + ty + j) * NV + n0 + tx];
    __syncthreads();
#pragma unroll
    for (int j = 0; j < 32; j += 8)
        g_wt[(size_t)(n0 + ty + j) * ND + k0 + tx] = __float2bfloat16(t[tx][ty + j]);
}

// ---------------------------------------------------------------------------
// Kernel 1: bf16 HMMA GEMM (CTA 128x128, 8 warps, warp tile 64x32).
//   K stages of 64, 3-deep cp.async pipeline, and DOUBLE-BUFFERED REGISTER
//   FRAGMENTS: kk+1's ldmatrix issues before kk's 16 MMAs, hiding LDSM latency.
// ---------------------------------------------------------------------------
#define KSTAGE 64
#define SROWB 144          // row stride in bytes (128 data + 16 pad)
#define PSTAGES 3
#define STAGE_BYTES (128 * SROWB)               // 18432 B per tile
#define GEMM_SMEM (PSTAGES * STAGE_BYTES * 2)   // 110592 B total

#define LOAD_FRAGS(sl, sAb, sBb, kbyte)                                         \
    do {                                                                        \
        _Pragma("unroll")                                                       \
        for (int mt = 0; mt < 4; mt++)                                          \
            LDSM_X4(af[sl][mt][0], af[sl][mt][1], af[sl][mt][2], af[sl][mt][3], \
                    (sAb) + aoff + mt * 16 * SROWB + (kbyte));                  \
        _Pragma("unroll")                                                       \
        for (int p = 0; p < 2; p++)                                             \
            LDSM_X4(bf[sl][p][0], bf[sl][p][1], bf[sl][p][2], bf[sl][p][3],     \
                    (sBb) + boff + p * 16 * SROWB + (kbyte));                   \
    } while (0)

#define DO_MMAS(sl)                                                             \
    do {                                                                        \
        _Pragma("unroll")                                                       \
        for (int mt = 0; mt < 4; mt++) {                                        \
            _Pragma("unroll")                                                   \
            for (int nt = 0; nt < 4; nt++) {                                    \
                int p = nt >> 1, h = (nt & 1) * 2;                              \
                MMA16816(acc[mt][nt], af[sl][mt][0], af[sl][mt][1],             \
                         af[sl][mt][2], af[sl][mt][3], bf[sl][p][h],            \
                         bf[sl][p][h + 1]);                                     \
            }                                                                   \
        }                                                                       \
    } while (0)

__global__ __launch_bounds__(256) void gemm_hmma_kernel(const float* __restrict__ bias) {
    extern __shared__ __align__(16) char smem[];

    const int tid = threadIdx.x, wid = tid >> 5, lane = tid & 31;
    const int bx = blockIdx.x;           // N tile (0..7)
    const int by = blockIdx.y;           // M tile (0..127)
    const int mBase = by * 128, nBase = bx * 128;
    const int wm = (wid >> 2) * 64;      // warp M offset in tile
    const int wn = (wid & 3) * 32;       // warp N offset in tile

    const __nv_bfloat16* Ag = g_xb + (size_t)mBase * ND;
    const __nv_bfloat16* Bg = g_wt + (size_t)nBase * ND;

    uint32_t sA0 = smem_u32(smem);
    uint32_t sB0 = sA0 + PSTAGES * STAGE_BYTES;

    const int NSTG = ND / KSTAGE;   // 8

    // prologue: stages 0,1
#pragma unroll
    for (int s = 0; s < PSTAGES - 1; s++) {
        const __nv_bfloat16* Ags = Ag + s * KSTAGE;
        const __nv_bfloat16* Bgs = Bg + s * KSTAGE;
        uint32_t sAn = sA0 + s * STAGE_BYTES;
        uint32_t sBn = sB0 + s * STAGE_BYTES;
#pragma unroll
        for (int j = 0; j < 4; j++) {
            int idx = tid + j * 256;
            int r = idx >> 3, c = idx & 7;
            CP_ASYNC16(sAn + r * SROWB + c * 16, Ags + (size_t)r * ND + c * 8);
            CP_ASYNC16(sBn + r * SROWB + c * 16, Bgs + (size_t)r * ND + c * 8);
        }
        CP_COMMIT();
    }

    float acc[4][4][4];
#pragma unroll
    for (int i = 0; i < 4; i++)
#pragma unroll
        for (int j = 0; j < 4; j++)
#pragma unroll
            for (int r = 0; r < 4; r++) acc[i][j][r] = 0.f;

    uint32_t af[2][4][4], bf[2][2][4];   // double-buffered fragments

    uint32_t aoff = (uint32_t)((wm + (lane & 15)) * SROWB + (lane >> 4) * 16);
    uint32_t boff = (uint32_t)((wn + ((lane >> 4) & 1) * 8 + (lane & 7)) * SROWB +
                               ((lane >> 3) & 1) * 16);

#pragma unroll 1
    for (int ks = 0; ks < NSTG; ks++) {
        int buf = ks % PSTAGES;
        CP_WAIT1();             // stage ks arrived
        __syncthreads();        // recycled buffer's readers are done

        int sf = ks + PSTAGES - 1;      // stage to prefetch
        if (sf < NSTG) {
            int nb = sf % PSTAGES;
            const __nv_bfloat16* Ags = Ag + sf * KSTAGE;
            const __nv_bfloat16* Bgs = Bg + sf * KSTAGE;
            uint32_t sAn = sA0 + nb * STAGE_BYTES;
            uint32_t sBn = sB0 + nb * STAGE_BYTES;
#pragma unroll
            for (int j = 0; j < 4; j++) {
                int idx = tid + j * 256;
                int r = idx >> 3, c = idx & 7;
                CP_ASYNC16(sAn + r * SROWB + c * 16, Ags + (size_t)r * ND + c * 8);
                CP_ASYNC16(sBn + r * SROWB + c * 16, Bgs + (size_t)r * ND + c * 8);
            }
        }
        CP_COMMIT();

        uint32_t sAb = sA0 + buf * STAGE_BYTES;
        uint32_t sBb = sB0 + buf * STAGE_BYTES;

        LOAD_FRAGS(0, sAb, sBb, 0);          // kk=0 fragments
#pragma unroll
        for (int kk = 0; kk < 4; kk++) {
            int cur = kk & 1;
            if (kk < 3) {
                if (cur) LOAD_FRAGS(0, sAb, sBb, (kk + 1) * 32);
                else     LOAD_FRAGS(1, sAb, sBb, (kk + 1) * 32);
            }
            if (cur) DO_MMAS(1);
            else     DO_MMAS(0);
        }
    }

    // epilogue: +bias, store fp32 logits
    const float* bi = bias + nBase + wn;
#pragma unroll
    for (int mt = 0; mt < 4; mt++) {
        int r0 = mBase + wm + mt * 16 + (lane >> 2);
#pragma unroll
        for (int nt = 0; nt < 4; nt++) {
            int c = nt * 8 + (lane & 3) * 2;
            float b0 = bi[c], b1 = bi[c + 1];
            float2 v0 = make_float2(acc[mt][nt][0] + b0, acc[mt][nt][1] + b1);
            float2 v1 = make_float2(acc[mt][nt][2] + b0, acc[mt][nt][3] + b1);
            *(float2*)(g_logits + (size_t)r0 * NV + nBase + wn + c) = v0;
            *(float2*)(g_logits + (size_t)(r0 + 8) * NV + nBase + wn + c) = v1;
        }
    }
}

// ---------------------------------------------------------------------------
// Kernel 2: per-row softmax over V -> compact row [pblank, podd[0..127], 0s]
// ---------------------------------------------------------------------------
__global__ __launch_bounds__(256) void softmax_kernel(const int* __restrict__ target) {
    int warp = threadIdx.x >> 5, lane = threadIdx.x & 31;
    int row = blockIdx.x * 8 + warp;
    int b = row >> 9;
    const float* lg = g_logits + (size_t)row * NV;

    float m = -CUDART_INF_F;
    float4 v[8];
#pragma unroll
    for (int i = 0; i < 8; i++) {
        v[i] = *(const float4*)(lg + i * 128 + lane * 4);
        m = fmaxf(m, fmaxf(fmaxf(v[i].x, v[i].y), fmaxf(v[i].z, v[i].w)));
    }
#pragma unroll
    for (int o = 16; o > 0; o >>= 1) m = fmaxf(m, __shfl_xor_sync(0xffffffffu, m, o));

    float se = 0.f;
#pragma unroll
    for (int i = 0; i < 8; i++)
        se += __expf(v[i].x - m) + __expf(v[i].y - m) + __expf(v[i].z - m) + __expf(v[i].w - m);
#pragma unroll
    for (int o = 16; o > 0; o >>= 1) se += __shfl_xor_sync(0xffffffffu, se, o);

    float inv = 1.f / se;

    float* P = g_pc + (size_t)row * PROW;
    const int* tg = target + b * NL;
#pragma unroll
    for (int j0 = 0; j0 < NL; j0 += 32) {
        int j = j0 + lane;
        int lab = tg[j];
        P[1 + j] = __expf(lg[lab] - m) * inv;
    }
    if (lane == 0) P[0] = __expf(lg[0] - m) * inv;   // blank
    if (lane >= 1 && lane <= 3) P[128 + lane] = 0.f; // slots 129..131 = 0
}

// ---------------------------------------------------------------------------
// Kernel 3: CTC forward recursion, probability domain, compact rows.
//   Per-lane index table: even s -> slot 0 (blank), odd s -> 1+(s>>1),
//   out-of-range -> slot 130 (zero). Rescale every 4 steps by exact 2^k.
// ---------------------------------------------------------------------------
#define CDEPTH 7

__global__ __launch_bounds__(32) void ctc_kernel(const int* __restrict__ target,
                                                 const int* __restrict__ in_len,
                                                 const int* __restrict__ tgt_len,
                                                 float* __restrict__ out) {
    int b = blockIdx.x;
    int lane = threadIdx.x;
    int s0 = lane * 9;
    const int* tg = target + b * NL;

    unsigned skipm = 0;
    int idx[9];
#pragma unroll
    for (int k = 0; k < 9; k++) {
        int s = s0 + k;
        idx[k] = (s < NS) ? ((s & 1) ? (1 + (s >> 1)) : 0) : 130;
        if (s >= 3 && s < NS && (s & 1)) {
            int j = (s - 1) >> 1;
            if (tg[j] != tg[j - 1]) skipm |= (1u << k);
        }
    }

    const float* P = g_pc + (size_t)b * NT * PROW;
    int TL = in_len[b];
    int tl = tgt_len[b];
    int send1 = 2 * tl - 1, send2 = 2 * tl;

    float a[9];
#pragma unroll
    for (int k = 0; k < 9; k++) {
        int s = s0 + k;
        a[k] = (s < 2) ? P[idx[k]] : 0.f;
    }

    int escale = 0;            // true alpha = a * 2^escale
    float ll = -CUDART_INF_F;
    const float LN2 = 0.6931471805599453f;

    if (TL == 1) {
        float part = 0.f;
#pragma unroll
        for (int k = 0; k < 9; k++) {
            int s = s0 + k;
            part += (s == send1 || s == send2) ? a[k] : 0.f;
        }
#pragma unroll
        for (int o = 16; o > 0; o >>= 1) part += __shfl_xor_sync(0xffffffffu, part, o);
        ll = __logf(part);
    }

    float pf[CDEPTH][9];
#pragma unroll
    for (int u = 0; u < CDEPTH; u++) {
        const float* Pt = P + (size_t)(u + 1) * PROW;
#pragma unroll
        for (int k = 0; k < 9; k++) pf[u][k] = Pt[idx[k]];
    }

#pragma unroll 1
    for (int tb = 1; tb < NT; tb += CDEPTH) {
#pragma unroll
        for (int u = 0; u < CDEPTH; u++) {
            int t = tb + u;

            float up1 = __shfl_up_sync(0xffffffffu, a[8], 1);
            float up2 = __shfl_up_sync(0xffffffffu, a[7], 1);
            if (lane == 0) { up1 = 0.f; up2 = 0.f; }

            float na[9];
#pragma unroll
            for (int k = 0; k < 9; k++) {
                float sm1 = (k >= 1) ? a[k - 1] : up1;
                float sm2 = (k >= 2) ? a[k - 2] : ((k == 1) ? up1 : up2);
                float c = a[k] + sm1;
                if ((skipm >> k) & 1u) c += sm2;
                na[k] = c * pf[u][k];
            }
#pragma unroll
            for (int k = 0; k < 9; k++) a[k] = na[k];

            if (t == TL - 1) {
                float part = 0.f;
#pragma unroll
                for (int k = 0; k < 9; k++) {
                    int s = s0 + k;
                    part += (s == send1 || s == send2) ? a[k] : 0.f;
                }
#pragma unroll
                for (int o = 16; o > 0; o >>= 1) part += __shfl_xor_sync(0xffffffffu, part, o);
                ll = (float)escale * LN2 + __logf(part);
            }

            if ((t & 3) == 3) {
                float tot = 0.f;
#pragma unroll
                for (int k = 0; k < 9; k++) tot += a[k];
#pragma unroll
                for (int o = 16; o > 0; o >>= 1) tot += __shfl_xor_sync(0xffffffffu, tot, o);
                if (tot > 0.f) {
                    unsigned E = (__float_as_uint(tot) >> 23) & 0xffu;
                    float sc = __uint_as_float((254u - E) << 23);   // exact 2^(127-E)
                    escale += (int)E - 127;
#pragma unroll
                    for (int k = 0; k < 9; k++) a[k] *= sc;
                }
            }

            int tn = t + CDEPTH;
            if (tn < NT) {
                const float* Pt = P + (size_t)tn * PROW;
#pragma unroll
                for (int k = 0; k < 9; k++) pf[u][k] = Pt[idx[k]];
            } else {
#pragma unroll
                for (int k = 0; k < 9; k++) pf[u][k] = 0.f;
            }
        }
    }

    if (lane == 0) {
        float nll = -ll;
        if (!(nll < 1e29f)) nll = 0.f;
        g_loss[b] = nll / fmaxf((float)tl, 1.f);
        __threadfence();
        int prev = atomicAdd(&g_cnt, 1);
        if (prev == NB - 1) {
            float s = 0.f;
#pragma unroll
            for (int i = 0; i < NB; i++) s += g_loss[i];
            out[0] = s * (1.f / NB);
            g_cnt = 0;   // reset for next graph replay (deterministic)
        }
    }
}

extern "C" void kernel_launch(void* const* d_in, const int* in_sizes, int n_in,
                              void* d_out, int out_size) {
    const float* x = (const float*)d_in[0];        // [B,T,D]
    const float* W = (const float*)d_in[1];        // [D,V]
    const float* bias = (const float*)d_in[2];     // [V]
    const int* target = (const int*)d_in[3];       // [B,L]
    const int* in_len = (const int*)d_in[4];       // [B]
    const int* tgt_len = (const int*)d_in[5];      // [B]

    cudaFuncSetAttribute(gemm_hmma_kernel,
                         cudaFuncAttributeMaxDynamicSharedMemorySize, GEMM_SMEM);

    convert_x_kernel<<<(NM * ND) / 4 / 256, 256>>>(x);
    {
        dim3 blk(32, 8), grd(NV / 32, ND / 32);
        convert_w_kernel<<<grd, blk>>>(W);
    }
    {
        dim3 gg(NV / 128, NM / 128);
        gemm_hmma_kernel<<<gg, 256, GEMM_SMEM>>>(bias);
    }
    softmax_kernel<<<NM / 8, 256>>>(target);
    ctc_kernel<<<NB, 32>>>(target, in_len, tgt_len, (float*)d_out);
}

// round 11
// speedup vs baseline: 1.2162x; 1.0494x over previous
#include <cuda_runtime.h>
#include <cuda_bf16.h>
#include <math_constants.h>
#include <cstdint>

#define NB 32
#define NT 512
#define ND 512
#define NV 1024
#define NL 128
#define NS 257      // 2*NL+1
#define PROW 132    // compact row: [pblank, podd[0..127], 0, 0, 0]
#define NM (NB*NT)  // 16384 rows

// Scratch (allocation-free per harness rules)
__device__ float g_logits[(size_t)NM * NV];          // 64 MB
__device__ float g_pc[(size_t)NM * PROW];            // 8.6 MB compact probs
__device__ float2 g_part[(size_t)NM * 32];           // 4 MB per-row/per-warp (max,sumexp)
__device__ float g_loss[NB];
__device__ int   g_cnt;                              // ctc completion counter
__device__ __nv_bfloat16 g_xb[(size_t)NM * ND];      // 16 MB  (x in bf16)
__device__ __nv_bfloat16 g_wt[(size_t)NV * ND];      // 1 MB   (W^T bf16 [V][D])

// ---------------------------------------------------------------------------
// PTX helpers (portable: cp.async sm_80+, ldmatrix sm_75+, mma.bf16 sm_80+)
// ---------------------------------------------------------------------------
__device__ __forceinline__ uint32_t smem_u32(const void* p) {
    uint32_t a;
    asm("{ .reg .u64 t; cvta.to.shared.u64 t, %1; cvt.u32.u64 %0, t; }" : "=r"(a) : "l"(p));
    return a;
}
#define CP_ASYNC16(dst, src) \
    asm volatile("cp.async.cg.shared.global [%0], [%1], 16;" :: "r"(dst), "l"(src))
#define CP_COMMIT() asm volatile("cp.async.commit_group;" ::: "memory")
#define CP_WAIT1()  asm volatile("cp.async.wait_group 1;" ::: "memory")

#define LDSM_X4(r0, r1, r2, r3, addr) \
    asm volatile("ldmatrix.sync.aligned.m8n8.x4.shared.b16 {%0,%1,%2,%3}, [%4];" \
                 : "=r"(r0), "=r"(r1), "=r"(r2), "=r"(r3) : "r"(addr))

#define MMA16816(d, a0, a1, a2, a3, b0, b1) \
    asm volatile("mma.sync.aligned.m16n8k16.row.col.f32.bf16.bf16.f32 " \
                 "{%0,%1,%2,%3}, {%4,%5,%6,%7}, {%8,%9}, {%0,%1,%2,%3};" \
                 : "+f"((d)[0]), "+f"((d)[1]), "+f"((d)[2]), "+f"((d)[3]) \
                 : "r"(a0), "r"(a1), "r"(a2), "r"(a3), "r"(b0), "r"(b1))

// ---------------------------------------------------------------------------
// Kernel 0: fused converts. Blocks [0, 8192): x -> bf16.
//           Blocks [8192, 8704): W[D][V] fp32 -> g_wt[V][D] bf16 (transpose).
// ---------------------------------------------------------------------------
__global__ __launch_bounds__(256) void convert_kernel(const float* __restrict__ x,
                                                      const float* __restrict__ W) {
    if (blockIdx.x < 8192) {
        size_t i = ((size_t)blockIdx.x * 256 + threadIdx.x) * 4;
        float4 v = *(const float4*)(x + i);
        *(__nv_bfloat162*)(g_xb + i) = __floats2bfloat162_rn(v.x, v.y);
        *(__nv_bfloat162*)(g_xb + i + 2) = __floats2bfloat162_rn(v.z, v.w);
    } else {
        __shared__ float t[32][33];
        int blk = blockIdx.x - 8192;          // 0..511
        int tx = threadIdx.x & 31, ty = threadIdx.x >> 5;
        int n0 = (blk & 31) * 32, k0 = (blk >> 5) * 32;
#pragma unroll
        for (int j = 0; j < 32; j += 8)
            t[ty + j][tx] = W[(size_t)(k0 + ty + j) * NV + n0 + tx];
        __syncthreads();
#pragma unroll
        for (int j = 0; j < 32; j += 8)
            g_wt[(size_t)(n0 + ty + j) * ND + k0 + tx] = __float2bfloat16(t[tx][ty + j]);
    }
}

// ---------------------------------------------------------------------------
// Kernel 1: bf16 HMMA GEMM (CTA 128x128, 8 warps, warp tile 64x32).
//   K stages of 64, 3-deep cp.async pipeline, double-buffered register
//   fragments. Epilogue ALSO emits per-warp softmax partials (max, sumexp)
//   per row, computed entirely in registers (no smem round-trip).
// ---------------------------------------------------------------------------
#define KSTAGE 64
#define SROWB 144          // row stride in bytes (128 data + 16 pad)
#define PSTAGES 3
#define STAGE_BYTES (128 * SROWB)               // 18432 B per tile
#define GEMM_SMEM (PSTAGES * STAGE_BYTES * 2)   // 110592 B total

#define LOAD_FRAGS(sl, sAb, sBb, kbyte)                                         \
    do {                                                                        \
        _Pragma("unroll")                                                       \
        for (int mt = 0; mt < 4; mt++)                                          \
            LDSM_X4(af[sl][mt][0], af[sl][mt][1], af[sl][mt][2], af[sl][mt][3], \
                    (sAb) + aoff + mt * 16 * SROWB + (kbyte));                  \
        _Pragma("unroll")                                                       \
        for (int p = 0; p < 2; p++)                                             \
            LDSM_X4(bf[sl][p][0], bf[sl][p][1], bf[sl][p][2], bf[sl][p][3],     \
                    (sBb) + boff + p * 16 * SROWB + (kbyte));                   \
    } while (0)

#define DO_MMAS(sl)                                                             \
    do {                                                                        \
        _Pragma("unroll")                                                       \
        for (int mt = 0; mt < 4; mt++) {                                        \
            _Pragma("unroll")                                                   \
            for (int nt = 0; nt < 4; nt++) {                                    \
                int p = nt >> 1, h = (nt & 1) * 2;                              \
                MMA16816(acc[mt][nt], af[sl][mt][0], af[sl][mt][1],             \
                         af[sl][mt][2], af[sl][mt][3], bf[sl][p][h],            \
                         bf[sl][p][h + 1]);                                     \
            }                                                                   \
        }                                                                       \
    } while (0)

__global__ __launch_bounds__(256) void gemm_hmma_kernel(const float* __restrict__ bias) {
    extern __shared__ __align__(16) char smem[];

    const int tid = threadIdx.x, wid = tid >> 5, lane = tid & 31;
    const int bx = blockIdx.x;           // N tile (0..7)
    const int by = blockIdx.y;           // M tile (0..127)
    const int mBase = by * 128, nBase = bx * 128;
    const int wm = (wid >> 2) * 64;      // warp M offset in tile
    const int wn = (wid & 3) * 32;       // warp N offset in tile

    const __nv_bfloat16* Ag = g_xb + (size_t)mBase * ND;
    const __nv_bfloat16* Bg = g_wt + (size_t)nBase * ND;

    uint32_t sA0 = smem_u32(smem);
    uint32_t sB0 = sA0 + PSTAGES * STAGE_BYTES;

    const int NSTG = ND / KSTAGE;   // 8

    // prologue: stages 0,1
#pragma unroll
    for (int s = 0; s < PSTAGES - 1; s++) {
        const __nv_bfloat16* Ags = Ag + s * KSTAGE;
        const __nv_bfloat16* Bgs = Bg + s * KSTAGE;
        uint32_t sAn = sA0 + s * STAGE_BYTES;
        uint32_t sBn = sB0 + s * STAGE_BYTES;
#pragma unroll
        for (int j = 0; j < 4; j++) {
            int idx = tid + j * 256;
            int r = idx >> 3, c = idx & 7;
            CP_ASYNC16(sAn + r * SROWB + c * 16, Ags + (size_t)r * ND + c * 8);
            CP_ASYNC16(sBn + r * SROWB + c * 16, Bgs + (size_t)r * ND + c * 8);
        }
        CP_COMMIT();
    }

    float acc[4][4][4];
#pragma unroll
    for (int i = 0; i < 4; i++)
#pragma unroll
        for (int j = 0; j < 4; j++)
#pragma unroll
            for (int r = 0; r < 4; r++) acc[i][j][r] = 0.f;

    uint32_t af[2][4][4], bf[2][2][4];   // double-buffered fragments

    uint32_t aoff = (uint32_t)((wm + (lane & 15)) * SROWB + (lane >> 4) * 16);
    uint32_t boff = (uint32_t)((wn + ((lane >> 4) & 1) * 8 + (lane & 7)) * SROWB +
                               ((lane >> 3) & 1) * 16);

#pragma unroll 1
    for (int ks = 0; ks < NSTG; ks++) {
        int buf = ks % PSTAGES;
        CP_WAIT1();             // stage ks arrived
        __syncthreads();        // recycled buffer's readers are done

        int sf = ks + PSTAGES - 1;      // stage to prefetch
        if (sf < NSTG) {
            int nb = sf % PSTAGES;
            const __nv_bfloat16* Ags = Ag + sf * KSTAGE;
            const __nv_bfloat16* Bgs = Bg + sf * KSTAGE;
            uint32_t sAn = sA0 + nb * STAGE_BYTES;
            uint32_t sBn = sB0 + nb * STAGE_BYTES;
#pragma unroll
            for (int j = 0; j < 4; j++) {
                int idx = tid + j * 256;
                int r = idx >> 3, c = idx & 7;
                CP_ASYNC16(sAn + r * SROWB + c * 16, Ags + (size_t)r * ND + c * 8);
                CP_ASYNC16(sBn + r * SROWB + c * 16, Bgs + (size_t)r * ND + c * 8);
            }
        }
        CP_COMMIT();

        uint32_t sAb = sA0 + buf * STAGE_BYTES;
        uint32_t sBb = sB0 + buf * STAGE_BYTES;

        LOAD_FRAGS(0, sAb, sBb, 0);
#pragma unroll
        for (int kk = 0; kk < 4; kk++) {
            int cur = kk & 1;
            if (kk < 3) {
                if (cur) LOAD_FRAGS(0, sAb, sBb, (kk + 1) * 32);
                else     LOAD_FRAGS(1, sAb, sBb, (kk + 1) * 32);
            }
            if (cur) DO_MMAS(1);
            else     DO_MMAS(0);
        }
    }

    // ---------------- epilogue ----------------
    // store fp32 logits (+bias) AND per-warp softmax partials from registers.
    const float* bi = bias + nBase + wn;
    const int pcol = bx * 4 + (wid & 3);         // this warp's partial column
#pragma unroll
    for (int mt = 0; mt < 4; mt++) {
        int r0 = mBase + wm + mt * 16 + (lane >> 2);
        float vA[8], vB[8];
#pragma unroll
        for (int nt = 0; nt < 4; nt++) {
            int c = nt * 8 + (lane & 3) * 2;
            float b0 = bi[c], b1 = bi[c + 1];
            vA[2 * nt]     = acc[mt][nt][0] + b0;
            vA[2 * nt + 1] = acc[mt][nt][1] + b1;
            vB[2 * nt]     = acc[mt][nt][2] + b0;
            vB[2 * nt + 1] = acc[mt][nt][3] + b1;
            *(float2*)(g_logits + (size_t)r0 * NV + nBase + wn + c) =
                make_float2(vA[2 * nt], vA[2 * nt + 1]);
            *(float2*)(g_logits + (size_t)(r0 + 8) * NV + nBase + wn + c) =
                make_float2(vB[2 * nt], vB[2 * nt + 1]);
        }
        // per-thread max over 8 values, then quad max (lanes sharing a row)
        float mA = vA[0], mB = vB[0];
#pragma unroll
        for (int j = 1; j < 8; j++) { mA = fmaxf(mA, vA[j]); mB = fmaxf(mB, vB[j]); }
#pragma unroll
        for (int o = 1; o <= 2; o <<= 1) {
            mA = fmaxf(mA, __shfl_xor_sync(0xffffffffu, mA, o));
            mB = fmaxf(mB, __shfl_xor_sync(0xffffffffu, mB, o));
        }
        float sA = 0.f, sB = 0.f;
#pragma unroll
        for (int j = 0; j < 8; j++) { sA += __expf(vA[j] - mA); sB += __expf(vB[j] - mB); }
#pragma unroll
        for (int o = 1; o <= 2; o <<= 1) {
            sA += __shfl_xor_sync(0xffffffffu, sA, o);
            sB += __shfl_xor_sync(0xffffffffu, sB, o);
        }
        if ((lane & 3) == 0) {
            g_part[(size_t)r0 * 32 + pcol] = make_float2(mA, sA);
            g_part[(size_t)(r0 + 8) * 32 + pcol] = make_float2(mB, sB);
        }
    }
}

// ---------------------------------------------------------------------------
// Kernel 2: combine partials + gather label logits -> compact prob rows
// ---------------------------------------------------------------------------
__global__ __launch_bounds__(256) void combine_kernel(const int* __restrict__ target) {
    int warp = threadIdx.x >> 5, lane = threadIdx.x & 31;
    int row = blockIdx.x * 8 + warp;
    int b = row >> 9;

    float2 ms = g_part[(size_t)row * 32 + lane];
    float m = ms.x;
#pragma unroll
    for (int o = 16; o > 0; o >>= 1) m = fmaxf(m, __shfl_xor_sync(0xffffffffu, m, o));
    float tot = ms.y * __expf(ms.x - m);
#pragma unroll
    for (int o = 16; o > 0; o >>= 1) tot += __shfl_xor_sync(0xffffffffu, tot, o);
    float inv = 1.f / tot;

    const float* lg = g_logits + (size_t)row * NV;
    float* P = g_pc + (size_t)row * PROW;
    const int* tg = target + b * NL;
#pragma unroll
    for (int j0 = 0; j0 < NL; j0 += 32) {
        int j = j0 + lane;
        int lab = tg[j];
        P[1 + j] = __expf(lg[lab] - m) * inv;
    }
    if (lane == 0) P[0] = __expf(lg[0] - m) * inv;   // blank
    if (lane >= 1 && lane <= 3) P[128 + lane] = 0.f; // slots 129..131 = 0
}

// ---------------------------------------------------------------------------
// Kernel 3: CTC forward recursion, probability domain, compact rows.
//   Rescale every 4 steps by exact 2^k using REDUX max (single instruction).
//   Prefetch depth 7 (511 = 73*7). Final mean fused via atomic counter.
// ---------------------------------------------------------------------------
#define CDEPTH 7

__global__ __launch_bounds__(32) void ctc_kernel(const int* __restrict__ target,
                                                 const int* __restrict__ in_len,
                                                 const int* __restrict__ tgt_len,
                                                 float* __restrict__ out) {
    int b = blockIdx.x;
    int lane = threadIdx.x;
    int s0 = lane * 9;
    const int* tg = target + b * NL;

    unsigned skipm = 0;
    int idx[9];
#pragma unroll
    for (int k = 0; k < 9; k++) {
        int s = s0 + k;
        idx[k] = (s < NS) ? ((s & 1) ? (1 + (s >> 1)) : 0) : 130;
        if (s >= 3 && s < NS && (s & 1)) {
            int j = (s - 1) >> 1;
            if (tg[j] != tg[j - 1]) skipm |= (1u << k);
        }
    }

    const float* P = g_pc + (size_t)b * NT * PROW;
    int TL = in_len[b];
    int tl = tgt_len[b];
    int send1 = 2 * tl - 1, send2 = 2 * tl;

    float a[9];
#pragma unroll
    for (int k = 0; k < 9; k++) {
        int s = s0 + k;
        a[k] = (s < 2) ? P[idx[k]] : 0.f;
    }

    int escale = 0;            // true alpha = a * 2^escale
    float ll = -CUDART_INF_F;
    const float LN2 = 0.6931471805599453f;

    if (TL == 1) {
        float part = 0.f;
#pragma unroll
        for (int k = 0; k < 9; k++) {
            int s = s0 + k;
            part += (s == send1 || s == send2) ? a[k] : 0.f;
        }
#pragma unroll
        for (int o = 16; o > 0; o >>= 1) part += __shfl_xor_sync(0xffffffffu, part, o);
        ll = __logf(part);
    }

    float pf[CDEPTH][9];
#pragma unroll
    for (int u = 0; u < CDEPTH; u++) {
        const float* Pt = P + (size_t)(u + 1) * PROW;
#pragma unroll
        for (int k = 0; k < 9; k++) pf[u][k] = Pt[idx[k]];
    }

#pragma unroll 1
    for (int tb = 1; tb < NT; tb += CDEPTH) {
#pragma unroll
        for (int u = 0; u < CDEPTH; u++) {
            int t = tb + u;

            float up1 = __shfl_up_sync(0xffffffffu, a[8], 1);
            float up2 = __shfl_up_sync(0xffffffffu, a[7], 1);
            if (lane == 0) { up1 = 0.f; up2 = 0.f; }

            float na[9];
#pragma unroll
            for (int k = 0; k < 9; k++) {
                float sm1 = (k >= 1) ? a[k - 1] : up1;
                float sm2 = (k >= 2) ? a[k - 2] : ((k == 1) ? up1 : up2);
                float c = a[k] + sm1;
                if ((skipm >> k) & 1u) c += sm2;
                na[k] = c * pf[u][k];
            }
#pragma unroll
            for (int k = 0; k < 9; k++) a[k] = na[k];

            if (t == TL - 1) {
                float part = 0.f;
#pragma unroll
                for (int k = 0; k < 9; k++) {
                    int s = s0 + k;
                    part += (s == send1 || s == send2) ? a[k] : 0.f;
                }
#pragma unroll
                for (int o = 16; o > 0; o >>= 1) part += __shfl_xor_sync(0xffffffffu, part, o);
                ll = (float)escale * LN2 + __logf(part);
            }

            if ((t & 3) == 3) {
                float mx = 0.f;
#pragma unroll
                for (int k = 0; k < 9; k++) mx = fmaxf(mx, a[k]);
                unsigned um = __reduce_max_sync(0xffffffffu, __float_as_uint(mx));
                if (um > 0u) {
                    unsigned E = um >> 23;               // a >= 0, exponent field
                    float sc = __uint_as_float((254u - E) << 23);   // exact 2^(127-E)
                    escale += (int)E - 127;
#pragma unroll
                    for (int k = 0; k < 9; k++) a[k] *= sc;
                }
            }

            int tn = t + CDEPTH;
            if (tn < NT) {
                const float* Pt = P + (size_t)tn * PROW;
#pragma unroll
                for (int k = 0; k < 9; k++) pf[u][k] = Pt[idx[k]];
            } else {
#pragma unroll
                for (int k = 0; k < 9; k++) pf[u][k] = 0.f;
            }
        }
    }

    if (lane == 0) {
        float nll = -ll;
        if (!(nll < 1e29f)) nll = 0.f;
        g_loss[b] = nll / fmaxf((float)tl, 1.f);
        __threadfence();
        int prev = atomicAdd(&g_cnt, 1);
        if (prev == NB - 1) {
            float s = 0.f;
#pragma unroll
            for (int i = 0; i < NB; i++) s += g_loss[i];
            out[0] = s * (1.f / NB);
            g_cnt = 0;   // reset for next graph replay (deterministic)
        }
    }
}

extern "C" void kernel_launch(void* const* d_in, const int* in_sizes, int n_in,
                              void* d_out, int out_size) {
    const float* x = (const float*)d_in[0];        // [B,T,D]
    const float* W = (const float*)d_in[1];        // [D,V]
    const float* bias = (const float*)d_in[2];     // [V]
    const int* target = (const int*)d_in[3];       // [B,L]
    const int* in_len = (const int*)d_in[4];       // [B]
    const int* tgt_len = (const int*)d_in[5];      // [B]

    cudaFuncSetAttribute(gemm_hmma_kernel,
                         cudaFuncAttributeMaxDynamicSharedMemorySize, GEMM_SMEM);

    convert_kernel<<<8192 + 512, 256>>>(x, W);
    {
        dim3 gg(NV / 128, NM / 128);
        gemm_hmma_kernel<<<gg, 256, GEMM_SMEM>>>(bias);
    }
    combine_kernel<<<NM / 8, 256>>>(target);
    ctc_kernel<<<NB, 32>>>(target, in_len, tgt_len, (float*)d_out);
}

// round 12
// speedup vs baseline: 1.2857x; 1.0571x over previous
#include <cuda_runtime.h>
#include <cuda_bf16.h>
#include <math_constants.h>
#include <cstdint>

#define NB 32
#define NT 512
#define ND 512
#define NV 1024
#define NL 128
#define NS 257      // 2*NL+1
#define PXROW 384   // expanded row: 32 lanes * 12 floats
#define NM (NB*NT)  // 16384 rows

// Scratch (allocation-free per harness rules)
__device__ float g_logits[(size_t)NM * NV];          // 64 MB
__device__ float g_px[(size_t)NM * PXROW];           // 25 MB lane-aligned probs
__device__ float2 g_part[(size_t)NM * 32];           // 4 MB per-row/per-warp (max,sumexp)
__device__ float g_loss[NB];
__device__ int   g_cnt;                              // ctc completion counter
__device__ __nv_bfloat16 g_xb[(size_t)NM * ND];      // 16 MB  (x in bf16)
__device__ __nv_bfloat16 g_wt[(size_t)NV * ND];      // 1 MB   (W^T bf16 [V][D])

// ---------------------------------------------------------------------------
// PTX helpers (portable: cp.async sm_80+, ldmatrix sm_75+, mma.bf16 sm_80+)
// ---------------------------------------------------------------------------
__device__ __forceinline__ uint32_t smem_u32(const void* p) {
    uint32_t a;
    asm("{ .reg .u64 t; cvta.to.shared.u64 t, %1; cvt.u32.u64 %0, t; }" : "=r"(a) : "l"(p));
    return a;
}
#define CP_ASYNC16(dst, src) \
    asm volatile("cp.async.cg.shared.global [%0], [%1], 16;" :: "r"(dst), "l"(src))
#define CP_COMMIT() asm volatile("cp.async.commit_group;" ::: "memory")
#define CP_WAIT1()  asm volatile("cp.async.wait_group 1;" ::: "memory")

#define LDSM_X4(r0, r1, r2, r3, addr) \
    asm volatile("ldmatrix.sync.aligned.m8n8.x4.shared.b16 {%0,%1,%2,%3}, [%4];" \
                 : "=r"(r0), "=r"(r1), "=r"(r2), "=r"(r3) : "r"(addr))

#define MMA16816(d, a0, a1, a2, a3, b0, b1) \
    asm volatile("mma.sync.aligned.m16n8k16.row.col.f32.bf16.bf16.f32 " \
                 "{%0,%1,%2,%3}, {%4,%5,%6,%7}, {%8,%9}, {%0,%1,%2,%3};" \
                 : "+f"((d)[0]), "+f"((d)[1]), "+f"((d)[2]), "+f"((d)[3]) \
                 : "r"(a0), "r"(a1), "r"(a2), "r"(a3), "r"(b0), "r"(b1))

// ---------------------------------------------------------------------------
// Kernel 0: fused converts. Blocks [0, 8192): x -> bf16.
//           Blocks [8192, 8704): W[D][V] fp32 -> g_wt[V][D] bf16 (transpose).
// ---------------------------------------------------------------------------
__global__ __launch_bounds__(256) void convert_kernel(const float* __restrict__ x,
                                                      const float* __restrict__ W) {
    if (blockIdx.x < 8192) {
        size_t i = ((size_t)blockIdx.x * 256 + threadIdx.x) * 4;
        float4 v = *(const float4*)(x + i);
        *(__nv_bfloat162*)(g_xb + i) = __floats2bfloat162_rn(v.x, v.y);
        *(__nv_bfloat162*)(g_xb + i + 2) = __floats2bfloat162_rn(v.z, v.w);
    } else {
        __shared__ float t[32][33];
        int blk = blockIdx.x - 8192;          // 0..511
        int tx = threadIdx.x & 31, ty = threadIdx.x >> 5;
        int n0 = (blk & 31) * 32, k0 = (blk >> 5) * 32;
#pragma unroll
        for (int j = 0; j < 32; j += 8)
            t[ty + j][tx] = W[(size_t)(k0 + ty + j) * NV + n0 + tx];
        __syncthreads();
#pragma unroll
        for (int j = 0; j < 32; j += 8)
            g_wt[(size_t)(n0 + ty + j) * ND + k0 + tx] = __float2bfloat16(t[tx][ty + j]);
    }
}

// ---------------------------------------------------------------------------
// Kernel 1: bf16 HMMA GEMM (CTA 128x128, 8 warps, warp tile 64x32).
//   K stages of 64, 3-deep cp.async pipeline, double-buffered register
//   fragments. Epilogue also emits per-warp softmax partials from registers.
// ---------------------------------------------------------------------------
#define KSTAGE 64
#define SROWB 144          // row stride in bytes (128 data + 16 pad)
#define PSTAGES 3
#define STAGE_BYTES (128 * SROWB)               // 18432 B per tile
#define GEMM_SMEM (PSTAGES * STAGE_BYTES * 2)   // 110592 B total

#define LOAD_FRAGS(sl, sAb, sBb, kbyte)                                         \
    do {                                                                        \
        _Pragma("unroll")                                                       \
        for (int mt = 0; mt < 4; mt++)                                          \
            LDSM_X4(af[sl][mt][0], af[sl][mt][1], af[sl][mt][2], af[sl][mt][3], \
                    (sAb) + aoff + mt * 16 * SROWB + (kbyte));                  \
        _Pragma("unroll")                                                       \
        for (int p = 0; p < 2; p++)                                             \
            LDSM_X4(bf[sl][p][0], bf[sl][p][1], bf[sl][p][2], bf[sl][p][3],     \
                    (sBb) + boff + p * 16 * SROWB + (kbyte));                   \
    } while (0)

#define DO_MMAS(sl)                                                             \
    do {                                                                        \
        _Pragma("unroll")                                                       \
        for (int mt = 0; mt < 4; mt++) {                                        \
            _Pragma("unroll")                                                   \
            for (int nt = 0; nt < 4; nt++) {                                    \
                int p = nt >> 1, h = (nt & 1) * 2;                              \
                MMA16816(acc[mt][nt], af[sl][mt][0], af[sl][mt][1],             \
                         af[sl][mt][2], af[sl][mt][3], bf[sl][p][h],            \
                         bf[sl][p][h + 1]);                                     \
            }                                                                   \
        }                                                                       \
    } while (0)

__global__ __launch_bounds__(256) void gemm_hmma_kernel(const float* __restrict__ bias) {
    extern __shared__ __align__(16) char smem[];

    const int tid = threadIdx.x, wid = tid >> 5, lane = tid & 31;
    const int bx = blockIdx.x;           // N tile (0..7)
    const int by = blockIdx.y;           // M tile (0..127)
    const int mBase = by * 128, nBase = bx * 128;
    const int wm = (wid >> 2) * 64;      // warp M offset in tile
    const int wn = (wid & 3) * 32;       // warp N offset in tile

    const __nv_bfloat16* Ag = g_xb + (size_t)mBase * ND;
    const __nv_bfloat16* Bg = g_wt + (size_t)nBase * ND;

    uint32_t sA0 = smem_u32(smem);
    uint32_t sB0 = sA0 + PSTAGES * STAGE_BYTES;

    const int NSTG = ND / KSTAGE;   // 8

    // prologue: stages 0,1
#pragma unroll
    for (int s = 0; s < PSTAGES - 1; s++) {
        const __nv_bfloat16* Ags = Ag + s * KSTAGE;
        const __nv_bfloat16* Bgs = Bg + s * KSTAGE;
        uint32_t sAn = sA0 + s * STAGE_BYTES;
        uint32_t sBn = sB0 + s * STAGE_BYTES;
#pragma unroll
        for (int j = 0; j < 4; j++) {
            int idx = tid + j * 256;
            int r = idx >> 3, c = idx & 7;
            CP_ASYNC16(sAn + r * SROWB + c * 16, Ags + (size_t)r * ND + c * 8);
            CP_ASYNC16(sBn + r * SROWB + c * 16, Bgs + (size_t)r * ND + c * 8);
        }
        CP_COMMIT();
    }

    float acc[4][4][4];
#pragma unroll
    for (int i = 0; i < 4; i++)
#pragma unroll
        for (int j = 0; j < 4; j++)
#pragma unroll
            for (int r = 0; r < 4; r++) acc[i][j][r] = 0.f;

    uint32_t af[2][4][4], bf[2][2][4];   // double-buffered fragments

    uint32_t aoff = (uint32_t)((wm + (lane & 15)) * SROWB + (lane >> 4) * 16);
    uint32_t boff = (uint32_t)((wn + ((lane >> 4) & 1) * 8 + (lane & 7)) * SROWB +
                               ((lane >> 3) & 1) * 16);

#pragma unroll 1
    for (int ks = 0; ks < NSTG; ks++) {
        int buf = ks % PSTAGES;
        CP_WAIT1();             // stage ks arrived
        __syncthreads();        // recycled buffer's readers are done

        int sf = ks + PSTAGES - 1;      // stage to prefetch
        if (sf < NSTG) {
            int nb = sf % PSTAGES;
            const __nv_bfloat16* Ags = Ag + sf * KSTAGE;
            const __nv_bfloat16* Bgs = Bg + sf * KSTAGE;
            uint32_t sAn = sA0 + nb * STAGE_BYTES;
            uint32_t sBn = sB0 + nb * STAGE_BYTES;
#pragma unroll
            for (int j = 0; j < 4; j++) {
                int idx = tid + j * 256;
                int r = idx >> 3, c = idx & 7;
                CP_ASYNC16(sAn + r * SROWB + c * 16, Ags + (size_t)r * ND + c * 8);
                CP_ASYNC16(sBn + r * SROWB + c * 16, Bgs + (size_t)r * ND + c * 8);
            }
        }
        CP_COMMIT();

        uint32_t sAb = sA0 + buf * STAGE_BYTES;
        uint32_t sBb = sB0 + buf * STAGE_BYTES;

        LOAD_FRAGS(0, sAb, sBb, 0);
#pragma unroll
        for (int kk = 0; kk < 4; kk++) {
            int cur = kk & 1;
            if (kk < 3) {
                if (cur) LOAD_FRAGS(0, sAb, sBb, (kk + 1) * 32);
                else     LOAD_FRAGS(1, sAb, sBb, (kk + 1) * 32);
            }
            if (cur) DO_MMAS(1);
            else     DO_MMAS(0);
        }
    }

    // ---------------- epilogue ----------------
    const float* bi = bias + nBase + wn;
    const int pcol = bx * 4 + (wid & 3);         // this warp's partial column
#pragma unroll
    for (int mt = 0; mt < 4; mt++) {
        int r0 = mBase + wm + mt * 16 + (lane >> 2);
        float vA[8], vB[8];
#pragma unroll
        for (int nt = 0; nt < 4; nt++) {
            int c = nt * 8 + (lane & 3) * 2;
            float b0 = bi[c], b1 = bi[c + 1];
            vA[2 * nt]     = acc[mt][nt][0] + b0;
            vA[2 * nt + 1] = acc[mt][nt][1] + b1;
            vB[2 * nt]     = acc[mt][nt][2] + b0;
            vB[2 * nt + 1] = acc[mt][nt][3] + b1;
            *(float2*)(g_logits + (size_t)r0 * NV + nBase + wn + c) =
                make_float2(vA[2 * nt], vA[2 * nt + 1]);
            *(float2*)(g_logits + (size_t)(r0 + 8) * NV + nBase + wn + c) =
                make_float2(vB[2 * nt], vB[2 * nt + 1]);
        }
        float mA = vA[0], mB = vB[0];
#pragma unroll
        for (int j = 1; j < 8; j++) { mA = fmaxf(mA, vA[j]); mB = fmaxf(mB, vB[j]); }
#pragma unroll
        for (int o = 1; o <= 2; o <<= 1) {
            mA = fmaxf(mA, __shfl_xor_sync(0xffffffffu, mA, o));
            mB = fmaxf(mB, __shfl_xor_sync(0xffffffffu, mB, o));
        }
        float sA = 0.f, sB = 0.f;
#pragma unroll
        for (int j = 0; j < 8; j++) { sA += __expf(vA[j] - mA); sB += __expf(vB[j] - mB); }
#pragma unroll
        for (int o = 1; o <= 2; o <<= 1) {
            sA += __shfl_xor_sync(0xffffffffu, sA, o);
            sB += __shfl_xor_sync(0xffffffffu, sB, o);
        }
        if ((lane & 3) == 0) {
            g_part[(size_t)r0 * 32 + pcol] = make_float2(mA, sA);
            g_part[(size_t)(r0 + 8) * 32 + pcol] = make_float2(mB, sB);
        }
    }
}

// ---------------------------------------------------------------------------
// Kernel 2: combine partials + gather -> lane-aligned expanded prob rows.
//   g_px[row][lane*12 + k] = p_ext(s = lane*9 + k) for k<9, 0 for k>=9.
// ---------------------------------------------------------------------------
__global__ __launch_bounds__(256) void combine_kernel(const int* __restrict__ target) {
    __shared__ float sm_plab[8][128];
    int warp = threadIdx.x >> 5, lane = threadIdx.x & 31;
    int row = blockIdx.x * 8 + warp;
    int b = row >> 9;

    float2 ms = g_part[(size_t)row * 32 + lane];
    float m = ms.x;
#pragma unroll
    for (int o = 16; o > 0; o >>= 1) m = fmaxf(m, __shfl_xor_sync(0xffffffffu, m, o));
    float tot = ms.y * __expf(ms.x - m);
#pragma unroll
    for (int o = 16; o > 0; o >>= 1) tot += __shfl_xor_sync(0xffffffffu, tot, o);
    float inv = 1.f / tot;

    const float* lg = g_logits + (size_t)row * NV;
    const int* tg = target + b * NL;
#pragma unroll
    for (int j0 = 0; j0 < NL; j0 += 32) {
        int j = j0 + lane;
        int lab = tg[j];
        sm_plab[warp][j] = __expf(lg[lab] - m) * inv;
    }
    float pblank = __expf(lg[0] - m) * inv;
    __syncwarp();

    float* PX = g_px + (size_t)row * PXROW + lane * 12;
    int s0 = lane * 9;
#pragma unroll
    for (int q = 0; q < 3; q++) {
        float4 o;
        float* op = (float*)&o;
#pragma unroll
        for (int e = 0; e < 4; e++) {
            int k = q * 4 + e;
            int s = s0 + k;
            float v = 0.f;
            if (k < 9 && s < NS)
                v = (s & 1) ? sm_plab[warp][s >> 1] : pblank;
            op[e] = v;
        }
        *(float4*)(PX + q * 4) = o;
    }
}

// ---------------------------------------------------------------------------
// Kernel 3: CTC forward recursion, probability domain, lane-aligned rows.
//   Per iter: 2x LDG.128 + 1x LDG.32 (single base), 2 shfl, 27 FMA-class ops.
//   Rescale every 4 steps by exact 2^k via REDUX max. Depth-7 prefetch.
// ---------------------------------------------------------------------------
#define CDEPTH 7

__global__ __launch_bounds__(32) void ctc_kernel(const int* __restrict__ target,
                                                 const int* __restrict__ in_len,
                                                 const int* __restrict__ tgt_len,
                                                 float* __restrict__ out) {
    int b = blockIdx.x;
    int lane = threadIdx.x;
    int s0 = lane * 9;
    const int* tg = target + b * NL;

    float skipf[9];
#pragma unroll
    for (int k = 0; k < 9; k++) {
        int s = s0 + k;
        skipf[k] = 0.f;
        if (s >= 3 && s < NS && (s & 1)) {
            int j = (s - 1) >> 1;
            if (tg[j] != tg[j - 1]) skipf[k] = 1.f;
        }
    }

    const float* P = g_px + (size_t)b * NT * PXROW + lane * 12;
    int TL = in_len[b];
    int tl = tgt_len[b];
    int send1 = 2 * tl - 1, send2 = 2 * tl;

    float a[9];
    {
        float4 q0 = *(const float4*)(P);
        float4 q1 = *(const float4*)(P + 4);
        float p8 = P[8];
        float v[9] = {q0.x, q0.y, q0.z, q0.w, q1.x, q1.y, q1.z, q1.w, p8};
#pragma unroll
        for (int k = 0; k < 9; k++) {
            int s = s0 + k;
            a[k] = (s < 2) ? v[k] : 0.f;
        }
    }

    int escale = 0;            // true alpha = a * 2^escale
    float ll = -CUDART_INF_F;
    const float LN2 = 0.6931471805599453f;

    if (TL == 1) {
        float part = 0.f;
#pragma unroll
        for (int k = 0; k < 9; k++) {
            int s = s0 + k;
            part += (s == send1 || s == send2) ? a[k] : 0.f;
        }
#pragma unroll
        for (int o = 16; o > 0; o >>= 1) part += __shfl_xor_sync(0xffffffffu, part, o);
        ll = __logf(part);
    }

    float pf[CDEPTH][9];
#pragma unroll
    for (int u = 0; u < CDEPTH; u++) {
        const float* Pt = P + (size_t)(u + 1) * PXROW;
        float4 q0 = *(const float4*)(Pt);
        float4 q1 = *(const float4*)(Pt + 4);
        pf[u][0] = q0.x; pf[u][1] = q0.y; pf[u][2] = q0.z; pf[u][3] = q0.w;
        pf[u][4] = q1.x; pf[u][5] = q1.y; pf[u][6] = q1.z; pf[u][7] = q1.w;
        pf[u][8] = Pt[8];
    }

#pragma unroll 1
    for (int tb = 1; tb < NT; tb += CDEPTH) {
#pragma unroll
        for (int u = 0; u < CDEPTH; u++) {
            int t = tb + u;

            float up1 = __shfl_up_sync(0xffffffffu, a[8], 1);
            float up2 = __shfl_up_sync(0xffffffffu, a[7], 1);
            if (lane == 0) { up1 = 0.f; up2 = 0.f; }

            float na[9];
#pragma unroll
            for (int k = 0; k < 9; k++) {
                float sm1 = (k >= 1) ? a[k - 1] : up1;
                float sm2 = (k >= 2) ? a[k - 2] : ((k == 1) ? up1 : up2);
                float c = a[k] + sm1;
                c = fmaf(skipf[k], sm2, c);
                na[k] = c * pf[u][k];
            }
#pragma unroll
            for (int k = 0; k < 9; k++) a[k] = na[k];

            if (t == TL - 1) {
                float part = 0.f;
#pragma unroll
                for (int k = 0; k < 9; k++) {
                    int s = s0 + k;
                    part += (s == send1 || s == send2) ? a[k] : 0.f;
                }
#pragma unroll
                for (int o = 16; o > 0; o >>= 1) part += __shfl_xor_sync(0xffffffffu, part, o);
                ll = (float)escale * LN2 + __logf(part);
            }

            if ((t & 3) == 3) {
                float mx = 0.f;
#pragma unroll
                for (int k = 0; k < 9; k++) mx = fmaxf(mx, a[k]);
                unsigned um = __reduce_max_sync(0xffffffffu, __float_as_uint(mx));
                if (um > 0u) {
                    unsigned E = um >> 23;               // a >= 0, exponent field
                    float sc = __uint_as_float((254u - E) << 23);   // exact 2^(127-E)
                    escale += (int)E - 127;
#pragma unroll
                    for (int k = 0; k < 9; k++) a[k] *= sc;
                }
            }

            int tn = t + CDEPTH;
            if (tn < NT) {
                const float* Pt = P + (size_t)tn * PXROW;
                float4 q0 = *(const float4*)(Pt);
                float4 q1 = *(const float4*)(Pt + 4);
                pf[u][0] = q0.x; pf[u][1] = q0.y; pf[u][2] = q0.z; pf[u][3] = q0.w;
                pf[u][4] = q1.x; pf[u][5] = q1.y; pf[u][6] = q1.z; pf[u][7] = q1.w;
                pf[u][8] = Pt[8];
            } else {
#pragma unroll
                for (int k = 0; k < 9; k++) pf[u][k] = 0.f;
            }
        }
    }

    if (lane == 0) {
        float nll = -ll;
        if (!(nll < 1e29f)) nll = 0.f;
        g_loss[b] = nll / fmaxf((float)tl, 1.f);
        __threadfence();
        int prev = atomicAdd(&g_cnt, 1);
        if (prev == NB - 1) {
            float s = 0.f;
#pragma unroll
            for (int i = 0; i < NB; i++) s += g_loss[i];
            out[0] = s * (1.f / NB);
            g_cnt = 0;   // reset for next graph replay (deterministic)
        }
    }
}

extern "C" void kernel_launch(void* const* d_in, const int* in_sizes, int n_in,
                              void* d_out, int out_size) {
    const float* x = (const float*)d_in[0];        // [B,T,D]
    const float* W = (const float*)d_in[1];        // [D,V]
    const float* bias = (const float*)d_in[2];     // [V]
    const int* target = (const int*)d_in[3];       // [B,L]
    const int* in_len = (const int*)d_in[4];       // [B]
    const int* tgt_len = (const int*)d_in[5];      // [B]

    cudaFuncSetAttribute(gemm_hmma_kernel,
                         cudaFuncAttributeMaxDynamicSharedMemorySize, GEMM_SMEM);

    convert_kernel<<<8192 + 512, 256>>>(x, W);
    {
        dim3 gg(NV / 128, NM / 128);
        gemm_hmma_kernel<<<gg, 256, GEMM_SMEM>>>(bias);
    }
    combine_kernel<<<NM / 8, 256>>>(target);
    ctc_kernel<<<NB, 32>>>(target, in_len, tgt_len, (float*)d_out);
}